// round 9
// baseline (speedup 1.0000x reference)
#include <cuda_runtime.h>

#define LQ  2048
#define SK  2048
#define NB  4
#define EMB 512
#define NH  16
#define HD  32
#define ROWS (LQ * NB)   // 8192

// Scratch (allocation-free rule: __device__ globals)
__device__ float g_Q[NB * NH * LQ * HD];   // [n,h,l,d]
__device__ float g_K[NB * NH * SK * HD];   // [n,h,s,d]
__device__ float g_V[NB * NH * SK * HD];
__device__ float g_O[ROWS * EMB];          // attention output, (l*NB+n, e) row-major

// ---------------------------------------------------------------------------
// tf32 helpers
// ---------------------------------------------------------------------------
__device__ __forceinline__ unsigned f2tf(float x) {
    unsigned r;
    asm("cvt.rna.tf32.f32 %0, %1;" : "=r"(r) : "f"(x));
    return r;
}
__device__ __forceinline__ float tf32f(float x) {
    return __uint_as_float(f2tf(x));
}
__device__ __forceinline__ void mma_tf32(float* c, const unsigned* a,
                                         unsigned b0, unsigned b1) {
    asm volatile(
        "mma.sync.aligned.m16n8k8.row.col.f32.tf32.tf32.f32 "
        "{%0,%1,%2,%3}, {%4,%5,%6,%7}, {%8,%9}, {%0,%1,%2,%3};"
        : "+f"(c[0]), "+f"(c[1]), "+f"(c[2]), "+f"(c[3])
        : "r"(a[0]), "r"(a[1]), "r"(a[2]), "r"(a[3]), "r"(b0), "r"(b1));
}

// ---------------------------------------------------------------------------
// 3xTF32 tensor-core GEMM: out[r,f] = sum_e A[r,e] * W[f,e] + bias[f]
// Block tile 128x64, BK=16, 128 threads = 4 warps (2 along M x 2 along N),
// warptile 64x32 (mi=4, ni=4) -> acc 64 regs, ~3 blocks/SM.
// Permuted fragment-native smem: a-frags = LDS.128, b-frags = LDS.64.
// ---------------------------------------------------------------------------
template<int MODE>
__global__ __launch_bounds__(128)
void gemm_mma_kernel(const float* __restrict__ Aq, const float* __restrict__ Ak,
                     const float* __restrict__ Av, const float* __restrict__ Wfull,
                     const float* __restrict__ bfull, float* __restrict__ outp)
{
    // A: 8 m-tiles x 2 kb x 32 lanes x 4 floats = 2048 floats (8KB) each
    // B: 8 n-tiles x 2 kb x 32 lanes x 2 floats = 1024 floats (4KB) each
    __shared__ float Ah_s[2048];
    __shared__ float Al_s[2048];
    __shared__ float Bh_s[1024];
    __shared__ float Bl_s[1024];

    const int tid    = threadIdx.x;
    const int warp   = tid >> 5;
    const int lane   = tid & 31;
    const int g      = lane >> 2;
    const int t      = lane & 3;
    const int warp_m = warp >> 1;   // 0..1
    const int warp_n = warp & 1;    // 0..1
    const int r0     = blockIdx.x * 128;
    const int f0     = blockIdx.y * 64;

    const float* A;
    const float* W;
    const float* bias;
    if (MODE == 0) {
        const int z = blockIdx.z;
        A    = (z == 0) ? Aq : (z == 1) ? Ak : Av;
        W    = Wfull + z * EMB * EMB;
        bias = bfull + z * EMB;
    } else {
        A    = g_O;
        W    = Wfull;
        bias = bfull;
    }

    const int rowBase = tid >> 2;          // 0..31
    const int kkL     = (tid & 3) << 2;    // 0,4,8,12

    float acc[4][4][4];
    #pragma unroll
    for (int mi = 0; mi < 4; mi++)
        #pragma unroll
        for (int ni = 0; ni < 4; ni++)
            #pragma unroll
            for (int j = 0; j < 4; j++) acc[mi][ni][j] = 0.f;

    // initial global prefetch
    float4 aReg[4], bReg[2];
    #pragma unroll
    for (int i = 0; i < 4; i++)
        aReg[i] = *(const float4*)(A + (size_t)(r0 + rowBase + i * 32) * EMB + kkL);
    #pragma unroll
    for (int i = 0; i < 2; i++)
        bReg[i] = *(const float4*)(W + (size_t)(f0 + rowBase + i * 32) * EMB + kkL);

    for (int k0 = 0; k0 < EMB; k0 += 16) {
        // ---- store prefetched tile to smem (permuted, hi/lo split) ----
        #pragma unroll
        for (int i = 0; i < 4; i++) {
            const int r  = rowBase + i * 32;
            const int mt = r >> 4;
            const int gg = r & 15;
            const float x[4] = {aReg[i].x, aReg[i].y, aReg[i].z, aReg[i].w};
            #pragma unroll
            for (int j = 0; j < 4; j++) {
                const int c  = kkL + j;
                const int kb = c >> 3;
                const int cc = c & 7;
                const int off = (((mt * 2 + kb) * 32) + ((gg & 7) * 4 + (cc & 3))) * 4
                                + ((cc >> 2) * 2 + (gg >> 3));
                const float h = tf32f(x[j]);
                Ah_s[off] = h;
                Al_s[off] = tf32f(x[j] - h);
            }
        }
        #pragma unroll
        for (int i = 0; i < 2; i++) {
            const int n  = rowBase + i * 32;
            const int nt = n >> 3;
            const int gb = n & 7;
            const float x[4] = {bReg[i].x, bReg[i].y, bReg[i].z, bReg[i].w};
            #pragma unroll
            for (int j = 0; j < 4; j++) {
                const int c  = kkL + j;
                const int kb = c >> 3;
                const int cc = c & 7;
                const int off = (((nt * 2 + kb) * 32) + (gb * 4 + (cc & 3))) * 2
                                + (cc >> 2);
                const float h = tf32f(x[j]);
                Bh_s[off] = h;
                Bl_s[off] = tf32f(x[j] - h);
            }
        }
        __syncthreads();

        // ---- issue next global loads (overlap with compute) ----
        if (k0 + 16 < EMB) {
            #pragma unroll
            for (int i = 0; i < 4; i++)
                aReg[i] = *(const float4*)(A + (size_t)(r0 + rowBase + i * 32) * EMB + k0 + 16 + kkL);
            #pragma unroll
            for (int i = 0; i < 2; i++)
                bReg[i] = *(const float4*)(W + (size_t)(f0 + rowBase + i * 32) * EMB + k0 + 16 + kkL);
        }

        // ---- compute ----
        #pragma unroll
        for (int kb = 0; kb < 2; kb++) {
            unsigned ah[4][4], al[4][4];
            #pragma unroll
            for (int mi = 0; mi < 4; mi++) {
                const int base = (((warp_m * 4 + mi) * 2 + kb) * 32 + lane) * 4;
                const float4 fh = *(const float4*)(Ah_s + base);
                const float4 fl = *(const float4*)(Al_s + base);
                ah[mi][0] = __float_as_uint(fh.x);
                ah[mi][1] = __float_as_uint(fh.y);
                ah[mi][2] = __float_as_uint(fh.z);
                ah[mi][3] = __float_as_uint(fh.w);
                al[mi][0] = __float_as_uint(fl.x);
                al[mi][1] = __float_as_uint(fl.y);
                al[mi][2] = __float_as_uint(fl.z);
                al[mi][3] = __float_as_uint(fl.w);
            }
            #pragma unroll
            for (int ni = 0; ni < 4; ni++) {
                const int baseB = (((warp_n * 4 + ni) * 2 + kb) * 32 + lane) * 2;
                const float2 bh = *(const float2*)(Bh_s + baseB);
                const float2 bl = *(const float2*)(Bl_s + baseB);
                const unsigned bh0 = __float_as_uint(bh.x);
                const unsigned bh1 = __float_as_uint(bh.y);
                const unsigned bl0 = __float_as_uint(bl.x);
                const unsigned bl1 = __float_as_uint(bl.y);
                #pragma unroll
                for (int mi = 0; mi < 4; mi++) {
                    mma_tf32(acc[mi][ni], ah[mi], bh0, bh1);
                    mma_tf32(acc[mi][ni], ah[mi], bl0, bl1);
                    mma_tf32(acc[mi][ni], al[mi], bh0, bh1);
                }
            }
        }
        __syncthreads();
    }

    // ---- epilogue: c0=(g,2t) c1=(g,2t+1) c2=(g+8,2t) c3=(g+8,2t+1) ----
    #pragma unroll
    for (int mi = 0; mi < 4; mi++) {
        const int rA = r0 + warp_m * 64 + mi * 16 + g;
        const int rB = rA + 8;
        #pragma unroll
        for (int ni = 0; ni < 4; ni++) {
            const float* c = acc[mi][ni];
            const int f  = f0 + warp_n * 32 + ni * 8 + 2 * t;
            const float b0 = bias[f];
            const float b1 = bias[f + 1];
            if (MODE == 0) {
                float* dst = (blockIdx.z == 0) ? g_Q : (blockIdx.z == 1) ? g_K : g_V;
                const int h = f >> 5;
                const int d = f & 31;
                {
                    const int l = rA >> 2, n = rA & 3;
                    *(float2*)(dst + ((size_t)(n * NH + h) * LQ + l) * HD + d) =
                        make_float2(c[0] + b0, c[1] + b1);
                }
                {
                    const int l = rB >> 2, n = rB & 3;
                    *(float2*)(dst + ((size_t)(n * NH + h) * LQ + l) * HD + d) =
                        make_float2(c[2] + b0, c[3] + b1);
                }
            } else {
                *(float2*)(outp + (size_t)rA * EMB + f) = make_float2(c[0] + b0, c[1] + b1);
                *(float2*)(outp + (size_t)rB * EMB + f) = make_float2(c[2] + b0, c[3] + b1);
            }
        }
    }
}

// ---------------------------------------------------------------------------
// LayerNorm over D=32 for K and V (one warp per row)
// ---------------------------------------------------------------------------
__global__ __launch_bounds__(256)
void ln_kernel(const float* __restrict__ w, const float* __restrict__ b)
{
    const int gw   = (blockIdx.x * blockDim.x + threadIdx.x) >> 5;
    const int lane = threadIdx.x & 31;
    const int R    = NB * NH * SK;
    if (gw >= 2 * R) return;
    float* X      = (gw < R) ? g_K : g_V;
    const int row = (gw < R) ? gw : gw - R;

    float x = X[(size_t)row * HD + lane];
    float s = x;
    #pragma unroll
    for (int o = 16; o; o >>= 1) s += __shfl_xor_sync(0xffffffffu, s, o);
    const float mu = s * (1.0f / HD);
    const float dv = x - mu;
    float vv = dv * dv;
    #pragma unroll
    for (int o = 16; o; o >>= 1) vv += __shfl_xor_sync(0xffffffffu, vv, o);
    const float inv = rsqrtf(vv * (1.0f / HD) + 1e-5f);
    X[(size_t)row * HD + lane] = dv * inv * w[lane] + b[lane];
}

// ---------------------------------------------------------------------------
// Flash attention, tf32 mma.sync, 3xTF32-compensated QK, single-tf32 PV.
// Block 128 thr (4 warps); each warp 16 q rows; block = 64 q rows.
// S-chunks of 64. K (hi/lo) and V in fragment-native permuted smem:
// K-frags = LDS.64 (x2), V-frags = LDS.64. exp2-domain softmax.
// ---------------------------------------------------------------------------
__global__ __launch_bounds__(128)
void attn_mma_kernel(const float* __restrict__ scaling)
{
    __shared__ float Khs[2048];   // [(nd*4+ks)*32+lane]*2+comp   nd<8, ks<4
    __shared__ float Kls[2048];
    __shared__ float Vvs[2048];   // [(kst*4+nd)*32+lane]*2+comp  kst<8, nd<4

    const int tid  = threadIdx.x;
    const int warp = tid >> 5;
    const int lane = tid & 31;
    const int g    = lane >> 2;
    const int t    = lane & 3;
    const int nh   = blockIdx.y;   // n*NH + h
    const int h    = nh & (NH - 1);
    const float betaL = scaling[h] * 1.4426950408889634f;
    const int q0   = blockIdx.x * 64 + warp * 16;

    // Q fragments (4 k-steps over D=32), beta*log2e-scaled, hi/lo tf32 split
    const float* Qp = g_Q + ((size_t)nh * LQ + q0) * HD;
    unsigned aqh[4][4], aql[4][4];
    #pragma unroll
    for (int ks = 0; ks < 4; ks++) {
        const float q00 = Qp[(size_t)g       * HD + ks * 8 + t]     * betaL;
        const float q10 = Qp[(size_t)(g + 8) * HD + ks * 8 + t]     * betaL;
        const float q01 = Qp[(size_t)g       * HD + ks * 8 + t + 4] * betaL;
        const float q11 = Qp[(size_t)(g + 8) * HD + ks * 8 + t + 4] * betaL;
        aqh[ks][0] = f2tf(q00);
        aqh[ks][1] = f2tf(q10);
        aqh[ks][2] = f2tf(q01);
        aqh[ks][3] = f2tf(q11);
        aql[ks][0] = f2tf(q00 - __uint_as_float(aqh[ks][0]));
        aql[ks][1] = f2tf(q10 - __uint_as_float(aqh[ks][1]));
        aql[ks][2] = f2tf(q01 - __uint_as_float(aqh[ks][2]));
        aql[ks][3] = f2tf(q11 - __uint_as_float(aqh[ks][3]));
    }

    float m0 = -1e30f, m1 = -1e30f, l0 = 0.f, l1 = 0.f;
    float o[4][4];
    #pragma unroll
    for (int nd = 0; nd < 4; nd++)
        #pragma unroll
        for (int j = 0; j < 4; j++) o[nd][j] = 0.f;

    const float* Kb = g_K + (size_t)nh * SK * HD;
    const float* Vb = g_V + (size_t)nh * SK * HD;
    const int sRow = tid >> 3;          // 0..15
    const int dCol = (tid & 7) << 2;    // 0,4,...,28

    for (int s0 = 0; s0 < SK; s0 += 64) {
        // ---- cooperative load: 64x32 K (hi/lo) + V into permuted smem ----
        #pragma unroll
        for (int i = 0; i < 4; i++) {
            const int s = sRow + i * 16;
            const int ndK = s >> 3, gK = s & 7;
            const float4 kv = *(const float4*)(Kb + (size_t)(s0 + s) * HD + dCol);
            const float kx[4] = {kv.x, kv.y, kv.z, kv.w};
            #pragma unroll
            for (int j = 0; j < 4; j++) {
                const int d = dCol + j;
                const int ks_ = d >> 3, cc = d & 7;
                const int off = ((ndK * 4 + ks_) * 32 + gK * 4 + (cc & 3)) * 2 + (cc >> 2);
                const float hh = tf32f(kx[j]);
                Khs[off] = hh;
                Kls[off] = tf32f(kx[j] - hh);
            }
            const int kstV = s >> 3, ssV = s & 7;
            const int tV = ssV & 3, compV = ssV >> 2;
            const float4 vv = *(const float4*)(Vb + (size_t)(s0 + s) * HD + dCol);
            const float vx[4] = {vv.x, vv.y, vv.z, vv.w};
            #pragma unroll
            for (int j = 0; j < 4; j++) {
                const int d = dCol + j;
                const int ndV = d >> 3, gV = d & 7;
                Vvs[((kstV * 4 + ndV) * 32 + gV * 4 + tV) * 2 + compV] = tf32f(vx[j]);
            }
        }
        __syncthreads();

        // ---- QK scores (3xTF32): 8 n-tiles of 16x8 ----
        float sc[8][4];
        #pragma unroll
        for (int nd = 0; nd < 8; nd++) {
            sc[nd][0] = sc[nd][1] = sc[nd][2] = sc[nd][3] = 0.f;
            #pragma unroll
            for (int ks = 0; ks < 4; ks++) {
                const int baseK = ((nd * 4 + ks) * 32 + lane) * 2;
                const float2 bh = *(const float2*)(Khs + baseK);
                const float2 bl = *(const float2*)(Kls + baseK);
                const unsigned bh0 = __float_as_uint(bh.x);
                const unsigned bh1 = __float_as_uint(bh.y);
                const unsigned bl0 = __float_as_uint(bl.x);
                const unsigned bl1 = __float_as_uint(bl.y);
                mma_tf32(sc[nd], aqh[ks], bh0, bh1);
                mma_tf32(sc[nd], aqh[ks], bl0, bl1);
                mma_tf32(sc[nd], aql[ks], bh0, bh1);
            }
        }

        // ---- online softmax (exp2 domain) ----
        float t0 = -1e30f, t1 = -1e30f;
        #pragma unroll
        for (int nd = 0; nd < 8; nd++) {
            t0 = fmaxf(t0, fmaxf(sc[nd][0], sc[nd][1]));
            t1 = fmaxf(t1, fmaxf(sc[nd][2], sc[nd][3]));
        }
        t0 = fmaxf(t0, __shfl_xor_sync(0xffffffffu, t0, 1));
        t0 = fmaxf(t0, __shfl_xor_sync(0xffffffffu, t0, 2));
        t1 = fmaxf(t1, __shfl_xor_sync(0xffffffffu, t1, 1));
        t1 = fmaxf(t1, __shfl_xor_sync(0xffffffffu, t1, 2));

        const float nm0 = fmaxf(m0, t0);
        const float nm1 = fmaxf(m1, t1);
        const float c0  = exp2f(m0 - nm0);
        const float c1  = exp2f(m1 - nm1);

        float rs0 = 0.f, rs1 = 0.f;
        #pragma unroll
        for (int nd = 0; nd < 8; nd++) {
            sc[nd][0] = exp2f(sc[nd][0] - nm0);
            sc[nd][1] = exp2f(sc[nd][1] - nm0);
            sc[nd][2] = exp2f(sc[nd][2] - nm1);
            sc[nd][3] = exp2f(sc[nd][3] - nm1);
            rs0 += sc[nd][0] + sc[nd][1];
            rs1 += sc[nd][2] + sc[nd][3];
        }
        rs0 += __shfl_xor_sync(0xffffffffu, rs0, 1);
        rs0 += __shfl_xor_sync(0xffffffffu, rs0, 2);
        rs1 += __shfl_xor_sync(0xffffffffu, rs1, 1);
        rs1 += __shfl_xor_sync(0xffffffffu, rs1, 2);

        l0 = l0 * c0 + rs0;
        l1 = l1 * c1 + rs1;
        #pragma unroll
        for (int nd = 0; nd < 4; nd++) {
            o[nd][0] *= c0; o[nd][1] *= c0;
            o[nd][2] *= c1; o[nd][3] *= c1;
        }
        m0 = nm0; m1 = nm1;

        // ---- PV (single tf32); P C-frag -> A-frag via intra-quad shuffles ----
        const int sA = t >> 1;
        const int sB = sA + 2;
        const bool odd = (t & 1);
        #pragma unroll
        for (int kst = 0; kst < 8; kst++) {
            const float p0 = sc[kst][0], p1 = sc[kst][1];
            const float p2 = sc[kst][2], p3 = sc[kst][3];
            const float x0 = __shfl_sync(0xffffffffu, p0, sA, 4);
            const float x1 = __shfl_sync(0xffffffffu, p1, sA, 4);
            const float y0 = __shfl_sync(0xffffffffu, p0, sB, 4);
            const float y1 = __shfl_sync(0xffffffffu, p1, sB, 4);
            const float z0 = __shfl_sync(0xffffffffu, p2, sA, 4);
            const float z1 = __shfl_sync(0xffffffffu, p3, sA, 4);
            const float w0 = __shfl_sync(0xffffffffu, p2, sB, 4);
            const float w1 = __shfl_sync(0xffffffffu, p3, sB, 4);
            unsigned ap[4];
            ap[0] = f2tf(odd ? x1 : x0);
            ap[1] = f2tf(odd ? z1 : z0);
            ap[2] = f2tf(odd ? y1 : y0);
            ap[3] = f2tf(odd ? w1 : w0);
            #pragma unroll
            for (int nd = 0; nd < 4; nd++) {
                const float2 bv = *(const float2*)(Vvs + ((kst * 4 + nd) * 32 + lane) * 2);
                const unsigned b0 = __float_as_uint(bv.x);
                const unsigned b1 = __float_as_uint(bv.y);
                mma_tf32(o[nd], ap, b0, b1);
            }
        }
        __syncthreads();
    }

    // ---- epilogue ----
    const float i0 = 1.0f / l0;
    const float i1 = 1.0f / l1;
    const int n = nh >> 4;
    float* op0 = g_O + ((size_t)(q0 + g)     * NB + n) * EMB + h * HD;
    float* op1 = g_O + ((size_t)(q0 + g + 8) * NB + n) * EMB + h * HD;
    #pragma unroll
    for (int nd = 0; nd < 4; nd++) {
        const int col = nd * 8 + 2 * t;
        *(float2*)(op0 + col) = make_float2(o[nd][0] * i0, o[nd][1] * i0);
        *(float2*)(op1 + col) = make_float2(o[nd][2] * i1, o[nd][3] * i1);
    }
}

// ---------------------------------------------------------------------------
extern "C" void kernel_launch(void* const* d_in, const int* in_sizes, int n_in,
                              void* d_out, int out_size)
{
    const float* query   = (const float*)d_in[0];
    const float* key_in  = (const float*)d_in[1];
    const float* value   = (const float*)d_in[2];
    const float* scaling = (const float*)d_in[3];
    const float* in_w    = (const float*)d_in[4];
    const float* in_b    = (const float*)d_in[5];
    const float* pn_w    = (const float*)d_in[6];
    const float* pn_b    = (const float*)d_in[7];
    const float* out_w   = (const float*)d_in[8];
    const float* out_b   = (const float*)d_in[9];
    float* out = (float*)d_out;

    // 1) QKV projections -> scratch in [n,h,len,d]
    dim3 gproj(ROWS / 128, EMB / 64, 3);
    gemm_mma_kernel<0><<<gproj, 128>>>(query, key_in, value, in_w, in_b, nullptr);

    // 2) LayerNorm K and V over D
    const int ln_rows = 2 * NB * NH * SK;
    ln_kernel<<<ln_rows / 8, 256>>>(pn_w, pn_b);

    // 3) Flash attention
    dim3 gattn(LQ / 64, NB * NH);
    attn_mma_kernel<<<gattn, 128>>>(scaling);

    // 4) Output projection -> d_out
    dim3 gout(ROWS / 128, EMB / 64, 1);
    gemm_mma_kernel<1><<<gout, 128>>>(nullptr, nullptr, nullptr, out_w, out_b, out);
}

// round 10
// speedup vs baseline: 1.1490x; 1.1490x over previous
#include <cuda_runtime.h>
#include <cuda_bf16.h>

#define LQ  2048
#define SK  2048
#define NB  4
#define EMB 512
#define NH  16
#define HD  32
#define ROWS (LQ * NB)   // 8192

// Scratch (allocation-free rule: __device__ globals)
__device__ float g_Q[NB * NH * LQ * HD];   // [n,h,l,d]
__device__ float g_K[NB * NH * SK * HD];   // [n,h,s,d]
__device__ float g_V[NB * NH * SK * HD];
__device__ float g_O[ROWS * EMB];          // attention output, (l*NB+n, e) row-major

// ---------------------------------------------------------------------------
// helpers
// ---------------------------------------------------------------------------
__device__ __forceinline__ unsigned f2tf(float x) {
    unsigned r;
    asm("cvt.rna.tf32.f32 %0, %1;" : "=r"(r) : "f"(x));
    return r;
}
__device__ __forceinline__ float tf32f(float x) {
    return __uint_as_float(f2tf(x));
}
// tf32 m16n8k8 (PV path)
__device__ __forceinline__ void mma_tf32(float* c, const unsigned* a,
                                         unsigned b0, unsigned b1) {
    asm volatile(
        "mma.sync.aligned.m16n8k8.row.col.f32.tf32.tf32.f32 "
        "{%0,%1,%2,%3}, {%4,%5,%6,%7}, {%8,%9}, {%0,%1,%2,%3};"
        : "+f"(c[0]), "+f"(c[1]), "+f"(c[2]), "+f"(c[3])
        : "r"(a[0]), "r"(a[1]), "r"(a[2]), "r"(a[3]), "r"(b0), "r"(b1));
}
// bf16 m16n8k16
__device__ __forceinline__ void mma_bf16(float* c, const unsigned* a,
                                         unsigned b0, unsigned b1) {
    asm volatile(
        "mma.sync.aligned.m16n8k16.row.col.f32.bf16.bf16.f32 "
        "{%0,%1,%2,%3}, {%4,%5,%6,%7}, {%8,%9}, {%0,%1,%2,%3};"
        : "+f"(c[0]), "+f"(c[1]), "+f"(c[2]), "+f"(c[3])
        : "r"(a[0]), "r"(a[1]), "r"(a[2]), "r"(a[3]), "r"(b0), "r"(b1));
}
// split (x,y) into packed bf16x2 hi and lo words (x in low half)
__device__ __forceinline__ void bsplit2(float x, float y, unsigned &hi, unsigned &lo) {
    __nv_bfloat162 h = __floats2bfloat162_rn(x, y);
    const float hx = __bfloat162float(h.x);
    const float hy = __bfloat162float(h.y);
    __nv_bfloat162 l = __floats2bfloat162_rn(x - hx, y - hy);
    hi = *reinterpret_cast<unsigned*>(&h);
    lo = *reinterpret_cast<unsigned*>(&l);
}

// ---------------------------------------------------------------------------
// 3xBF16 tensor-core GEMM: out[r,f] = sum_e A[r,e] * W[f,e] + bias[f]
// Block tile 128x64, BK=32, 256 threads = 8 warps (4M x 2N), warptile 32x32.
// Smem fragment-native, hi/lo interleaved:
//   A: ASm[((mt*2+ks)*32+lane)*8 + {0..3 hi, 4..7 lo}]  (16KB)
//   B: BSm[((nt*2+ks)*32+lane)*4 + {hi0,hi1,lo0,lo1}]   (8KB)
// ---------------------------------------------------------------------------
template<int MODE>
__global__ __launch_bounds__(256)
void gemm_mma_kernel(const float* __restrict__ Aq, const float* __restrict__ Ak,
                     const float* __restrict__ Av, const float* __restrict__ Wfull,
                     const float* __restrict__ bfull, float* __restrict__ outp)
{
    __shared__ unsigned ASm[4096];
    __shared__ unsigned BSm[2048];

    const int tid    = threadIdx.x;
    const int warp   = tid >> 5;
    const int lane   = tid & 31;
    const int g      = lane >> 2;
    const int t      = lane & 3;
    const int warp_m = warp >> 1;   // 0..3
    const int warp_n = warp & 1;    // 0..1
    const int r0     = blockIdx.x * 128;
    const int f0     = blockIdx.y * 64;

    const float* A;
    const float* W;
    const float* bias;
    if (MODE == 0) {
        const int z = blockIdx.z;
        A    = (z == 0) ? Aq : (z == 1) ? Ak : Av;
        W    = Wfull + z * EMB * EMB;
        bias = bfull + z * EMB;
    } else {
        A    = g_O;
        W    = Wfull;
        bias = bfull;
    }

    // A loading geometry: row = tid>>1 (0..127), 16 cols starting at (tid&1)*16
    const int loadRowA  = tid >> 1;
    const int ksA       = tid & 1;           // which k16 block
    const int mtA       = loadRowA >> 4;
    const int rrA       = loadRowA & 15;
    const int rowHalfA  = rrA >> 3;          // +0/+1 on reg idx base
    const int laneBaseA = (rrA & 7) * 4;
    // B loading geometry: row = tid>>2 (0..63), 8 cols starting at (tid&3)*8
    const int loadRowB  = tid >> 2;
    const int colBaseB  = (tid & 3) * 8;
    const int ksB       = colBaseB >> 4;
    const int rB_       = (colBaseB & 15) >> 3;   // reg 0 or 1
    const int ntB       = loadRowB >> 3;
    const int laneBaseB = (loadRowB & 7) * 4;

    float acc[2][4][4];
    #pragma unroll
    for (int mi = 0; mi < 2; mi++)
        #pragma unroll
        for (int ni = 0; ni < 4; ni++)
            #pragma unroll
            for (int j = 0; j < 4; j++) acc[mi][ni][j] = 0.f;

    // initial global prefetch
    float4 aReg[4], bReg[2];
    #pragma unroll
    for (int i = 0; i < 4; i++)
        aReg[i] = *(const float4*)(A + (size_t)(r0 + loadRowA) * EMB + ksA * 16 + i * 4);
    #pragma unroll
    for (int i = 0; i < 2; i++)
        bReg[i] = *(const float4*)(W + (size_t)(f0 + loadRowB) * EMB + colBaseB + i * 4);

    for (int k0 = 0; k0 < EMB; k0 += 32) {
        // ---- store prefetched tile (bf16 hi/lo split, fragment-native) ----
        #pragma unroll
        for (int i = 0; i < 4; i++) {
            // float4 covers cols cc = 4i .. 4i+3 within the k16 block ksA
            const int cc = 4 * i;
            const int r  = (cc >> 3) * 2 + rowHalfA;   // a-frag reg index
            const int tp = (cc & 7) >> 1;              // t of first pair
            const int idx = ((mtA * 2 + ksA) * 32 + laneBaseA + tp) * 8;
            unsigned hi, lo;
            bsplit2(aReg[i].x, aReg[i].y, hi, lo);
            ASm[idx + r]     = hi;
            ASm[idx + 4 + r] = lo;
            bsplit2(aReg[i].z, aReg[i].w, hi, lo);
            ASm[idx + 8 + r]     = hi;   // next pair: lane+1 -> +8 u32
            ASm[idx + 8 + 4 + r] = lo;
        }
        #pragma unroll
        for (int i = 0; i < 2; i++) {
            const int cc = (colBaseB & 15) + 4 * i;    // 0/4 or 8/12
            const int tp = (cc & 7) >> 1;
            const int idx = ((ntB * 2 + ksB) * 32 + laneBaseB + tp) * 4;
            unsigned hi, lo;
            bsplit2(bReg[i].x, bReg[i].y, hi, lo);
            BSm[idx + rB_]     = hi;
            BSm[idx + 2 + rB_] = lo;
            bsplit2(bReg[i].z, bReg[i].w, hi, lo);
            BSm[idx + 4 + rB_]     = hi;   // next pair lane+1
            BSm[idx + 4 + 2 + rB_] = lo;
        }
        __syncthreads();

        // ---- issue next global loads (overlap with compute) ----
        if (k0 + 32 < EMB) {
            #pragma unroll
            for (int i = 0; i < 4; i++)
                aReg[i] = *(const float4*)(A + (size_t)(r0 + loadRowA) * EMB + k0 + 32 + ksA * 16 + i * 4);
            #pragma unroll
            for (int i = 0; i < 2; i++)
                bReg[i] = *(const float4*)(W + (size_t)(f0 + loadRowB) * EMB + k0 + 32 + colBaseB + i * 4);
        }

        // ---- compute: 2 k16-steps, 3 MMAs per (mi,ni) per step ----
        #pragma unroll
        for (int ks = 0; ks < 2; ks++) {
            uint4 ah[2], al[2];
            #pragma unroll
            for (int mi = 0; mi < 2; mi++) {
                const int base = (((warp_m * 2 + mi) * 2 + ks) * 32 + lane) * 8;
                ah[mi] = *(const uint4*)(ASm + base);
                al[mi] = *(const uint4*)(ASm + base + 4);
            }
            #pragma unroll
            for (int ni = 0; ni < 4; ni++) {
                const uint4 bb = *(const uint4*)(BSm + (((warp_n * 4 + ni) * 2 + ks) * 32 + lane) * 4);
                #pragma unroll
                for (int mi = 0; mi < 2; mi++) {
                    mma_bf16(acc[mi][ni], &ah[mi].x, bb.x, bb.y);   // hi*hi
                    mma_bf16(acc[mi][ni], &ah[mi].x, bb.z, bb.w);   // hi*lo
                    mma_bf16(acc[mi][ni], &al[mi].x, bb.x, bb.y);   // lo*hi
                }
            }
        }
        __syncthreads();
    }

    // ---- epilogue: c0=(g,2t) c1=(g,2t+1) c2=(g+8,2t) c3=(g+8,2t+1) ----
    #pragma unroll
    for (int mi = 0; mi < 2; mi++) {
        const int rA = r0 + warp_m * 32 + mi * 16 + g;
        const int rB = rA + 8;
        #pragma unroll
        for (int ni = 0; ni < 4; ni++) {
            const float* c = acc[mi][ni];
            const int f  = f0 + warp_n * 32 + ni * 8 + 2 * t;
            const float b0 = bias[f];
            const float b1 = bias[f + 1];
            if (MODE == 0) {
                float* dst = (blockIdx.z == 0) ? g_Q : (blockIdx.z == 1) ? g_K : g_V;
                const int h = f >> 5;
                const int d = f & 31;
                {
                    const int l = rA >> 2, n = rA & 3;
                    *(float2*)(dst + ((size_t)(n * NH + h) * LQ + l) * HD + d) =
                        make_float2(c[0] + b0, c[1] + b1);
                }
                {
                    const int l = rB >> 2, n = rB & 3;
                    *(float2*)(dst + ((size_t)(n * NH + h) * LQ + l) * HD + d) =
                        make_float2(c[2] + b0, c[3] + b1);
                }
            } else {
                *(float2*)(outp + (size_t)rA * EMB + f) = make_float2(c[0] + b0, c[1] + b1);
                *(float2*)(outp + (size_t)rB * EMB + f) = make_float2(c[2] + b0, c[3] + b1);
            }
        }
    }
}

// ---------------------------------------------------------------------------
// LayerNorm over D=32 for K and V (one warp per row)
// ---------------------------------------------------------------------------
__global__ __launch_bounds__(256)
void ln_kernel(const float* __restrict__ w, const float* __restrict__ b)
{
    const int gw   = (blockIdx.x * blockDim.x + threadIdx.x) >> 5;
    const int lane = threadIdx.x & 31;
    const int R    = NB * NH * SK;
    if (gw >= 2 * R) return;
    float* X      = (gw < R) ? g_K : g_V;
    const int row = (gw < R) ? gw : gw - R;

    float x = X[(size_t)row * HD + lane];
    float s = x;
    #pragma unroll
    for (int o = 16; o; o >>= 1) s += __shfl_xor_sync(0xffffffffu, s, o);
    const float mu = s * (1.0f / HD);
    const float dv = x - mu;
    float vv = dv * dv;
    #pragma unroll
    for (int o = 16; o; o >>= 1) vv += __shfl_xor_sync(0xffffffffu, vv, o);
    const float inv = rsqrtf(vv * (1.0f / HD) + 1e-5f);
    X[(size_t)row * HD + lane] = dv * inv * w[lane] + b[lane];
}

// ---------------------------------------------------------------------------
// Flash attention: QK via 3xBF16 m16n8k16 (effectively fp32-accurate),
// PV via single tf32 m16n8k8. Block 128 thr (4 warps), 16 q rows/warp,
// S-chunks of 64. K hi/lo interleaved fragment-native; V tf32 frag-native.
// Q pre-scaled by beta*log2(e); softmax in exp2 domain.
// ---------------------------------------------------------------------------
__global__ __launch_bounds__(128)
void attn_mma_kernel(const float* __restrict__ scaling)
{
    __shared__ unsigned KS[2048];  // [((nd*2+ks)*32+lane)*4 + {h0,h1,l0,l1}]  8KB
    __shared__ float   Vvs[2048];  // [((kst*4+nd)*32+lane)*2 + comp]          8KB

    const int tid  = threadIdx.x;
    const int warp = tid >> 5;
    const int lane = tid & 31;
    const int g    = lane >> 2;
    const int t    = lane & 3;
    const int nh   = blockIdx.y;   // n*NH + h
    const int h    = nh & (NH - 1);
    const float betaL = scaling[h] * 1.4426950408889634f;
    const int q0   = blockIdx.x * 64 + warp * 16;

    // Q fragments: 2 k16-steps over D=32, bf16 hi/lo split, beta*log2e folded
    const float* Qp = g_Q + ((size_t)nh * LQ + q0) * HD;
    unsigned aqh[2][4], aql[2][4];
    #pragma unroll
    for (int ks = 0; ks < 2; ks++) {
        const int c0 = ks * 16 + 2 * t;
        const int c2 = c0 + 8;
        bsplit2(Qp[(size_t)g       * HD + c0] * betaL, Qp[(size_t)g       * HD + c0 + 1] * betaL,
                aqh[ks][0], aql[ks][0]);
        bsplit2(Qp[(size_t)(g + 8) * HD + c0] * betaL, Qp[(size_t)(g + 8) * HD + c0 + 1] * betaL,
                aqh[ks][1], aql[ks][1]);
        bsplit2(Qp[(size_t)g       * HD + c2] * betaL, Qp[(size_t)g       * HD + c2 + 1] * betaL,
                aqh[ks][2], aql[ks][2]);
        bsplit2(Qp[(size_t)(g + 8) * HD + c2] * betaL, Qp[(size_t)(g + 8) * HD + c2 + 1] * betaL,
                aqh[ks][3], aql[ks][3]);
    }

    float m0 = -1e30f, m1 = -1e30f, l0 = 0.f, l1 = 0.f;
    float o[4][4];
    #pragma unroll
    for (int nd = 0; nd < 4; nd++)
        #pragma unroll
        for (int j = 0; j < 4; j++) o[nd][j] = 0.f;

    const float* Kb = g_K + (size_t)nh * SK * HD;
    const float* Vb = g_V + (size_t)nh * SK * HD;
    const int sRow = tid >> 3;          // 0..15
    const int dCol = (tid & 7) << 2;    // 0,4,...,28
    const int ksK  = dCol >> 4;
    const int ccK  = dCol & 15;
    const int tK   = (ccK & 7) >> 1;    // t of first pair in this float4
    const int rK   = ccK >> 3;          // b-frag reg index (0/1)

    for (int s0 = 0; s0 < SK; s0 += 64) {
        // ---- cooperative load: 64x32 K (bf16 hi/lo) + V (tf32) ----
        #pragma unroll
        for (int i = 0; i < 4; i++) {
            const int s = sRow + i * 16;
            const int ndK = s >> 3, gK = s & 7;
            const float4 kv = *(const float4*)(Kb + (size_t)(s0 + s) * HD + dCol);
            {
                const int idx = ((ndK * 2 + ksK) * 32 + gK * 4 + tK) * 4;
                unsigned hi, lo;
                bsplit2(kv.x, kv.y, hi, lo);
                KS[idx + rK]     = hi;
                KS[idx + 2 + rK] = lo;
                bsplit2(kv.z, kv.w, hi, lo);
                KS[idx + 4 + rK]     = hi;   // next pair: lane+1
                KS[idx + 4 + 2 + rK] = lo;
            }
            const int kstV = s >> 3, ssV = s & 7;
            const int tV = ssV & 3, compV = ssV >> 2;
            const float4 vv = *(const float4*)(Vb + (size_t)(s0 + s) * HD + dCol);
            const float vx[4] = {vv.x, vv.y, vv.z, vv.w};
            #pragma unroll
            for (int j = 0; j < 4; j++) {
                const int d = dCol + j;
                const int ndV = d >> 3, gV = d & 7;
                Vvs[((kstV * 4 + ndV) * 32 + gV * 4 + tV) * 2 + compV] = tf32f(vx[j]);
            }
        }
        __syncthreads();

        // ---- QK scores (3xBF16): 8 n-tiles of 16x8, 2 k16-steps ----
        float sc[8][4];
        #pragma unroll
        for (int nd = 0; nd < 8; nd++) {
            sc[nd][0] = sc[nd][1] = sc[nd][2] = sc[nd][3] = 0.f;
            #pragma unroll
            for (int ks = 0; ks < 2; ks++) {
                const uint4 kb = *(const uint4*)(KS + ((nd * 2 + ks) * 32 + lane) * 4);
                mma_bf16(sc[nd], aqh[ks], kb.x, kb.y);   // hi*hi
                mma_bf16(sc[nd], aqh[ks], kb.z, kb.w);   // hi*lo
                mma_bf16(sc[nd], aql[ks], kb.x, kb.y);   // lo*hi
            }
        }

        // ---- online softmax (exp2 domain) ----
        float t0 = -1e30f, t1 = -1e30f;
        #pragma unroll
        for (int nd = 0; nd < 8; nd++) {
            t0 = fmaxf(t0, fmaxf(sc[nd][0], sc[nd][1]));
            t1 = fmaxf(t1, fmaxf(sc[nd][2], sc[nd][3]));
        }
        t0 = fmaxf(t0, __shfl_xor_sync(0xffffffffu, t0, 1));
        t0 = fmaxf(t0, __shfl_xor_sync(0xffffffffu, t0, 2));
        t1 = fmaxf(t1, __shfl_xor_sync(0xffffffffu, t1, 1));
        t1 = fmaxf(t1, __shfl_xor_sync(0xffffffffu, t1, 2));

        const float nm0 = fmaxf(m0, t0);
        const float nm1 = fmaxf(m1, t1);
        const float c0  = exp2f(m0 - nm0);
        const float c1  = exp2f(m1 - nm1);

        float rs0 = 0.f, rs1 = 0.f;
        #pragma unroll
        for (int nd = 0; nd < 8; nd++) {
            sc[nd][0] = exp2f(sc[nd][0] - nm0);
            sc[nd][1] = exp2f(sc[nd][1] - nm0);
            sc[nd][2] = exp2f(sc[nd][2] - nm1);
            sc[nd][3] = exp2f(sc[nd][3] - nm1);
            rs0 += sc[nd][0] + sc[nd][1];
            rs1 += sc[nd][2] + sc[nd][3];
        }
        rs0 += __shfl_xor_sync(0xffffffffu, rs0, 1);
        rs0 += __shfl_xor_sync(0xffffffffu, rs0, 2);
        rs1 += __shfl_xor_sync(0xffffffffu, rs1, 1);
        rs1 += __shfl_xor_sync(0xffffffffu, rs1, 2);

        l0 = l0 * c0 + rs0;
        l1 = l1 * c1 + rs1;
        #pragma unroll
        for (int nd = 0; nd < 4; nd++) {
            o[nd][0] *= c0; o[nd][1] *= c0;
            o[nd][2] *= c1; o[nd][3] *= c1;
        }
        m0 = nm0; m1 = nm1;

        // ---- PV (single tf32); P C-frag -> A-frag via intra-quad shuffles ----
        const int sA = t >> 1;
        const int sB = sA + 2;
        const bool odd = (t & 1);
        #pragma unroll
        for (int kst = 0; kst < 8; kst++) {
            const float p0 = sc[kst][0], p1 = sc[kst][1];
            const float p2 = sc[kst][2], p3 = sc[kst][3];
            const float x0 = __shfl_sync(0xffffffffu, p0, sA, 4);
            const float x1 = __shfl_sync(0xffffffffu, p1, sA, 4);
            const float y0 = __shfl_sync(0xffffffffu, p0, sB, 4);
            const float y1 = __shfl_sync(0xffffffffu, p1, sB, 4);
            const float z0 = __shfl_sync(0xffffffffu, p2, sA, 4);
            const float z1 = __shfl_sync(0xffffffffu, p3, sA, 4);
            const float w0 = __shfl_sync(0xffffffffu, p2, sB, 4);
            const float w1 = __shfl_sync(0xffffffffu, p3, sB, 4);
            unsigned ap[4];
            ap[0] = f2tf(odd ? x1 : x0);
            ap[1] = f2tf(odd ? z1 : z0);
            ap[2] = f2tf(odd ? y1 : y0);
            ap[3] = f2tf(odd ? w1 : w0);
            #pragma unroll
            for (int nd = 0; nd < 4; nd++) {
                const float2 bv = *(const float2*)(Vvs + ((kst * 4 + nd) * 32 + lane) * 2);
                const unsigned b0 = __float_as_uint(bv.x);
                const unsigned b1 = __float_as_uint(bv.y);
                mma_tf32(o[nd], ap, b0, b1);
            }
        }
        __syncthreads();
    }

    // ---- epilogue ----
    const float i0 = 1.0f / l0;
    const float i1 = 1.0f / l1;
    const int n = nh >> 4;
    float* op0 = g_O + ((size_t)(q0 + g)     * NB + n) * EMB + h * HD;
    float* op1 = g_O + ((size_t)(q0 + g + 8) * NB + n) * EMB + h * HD;
    #pragma unroll
    for (int nd = 0; nd < 4; nd++) {
        const int col = nd * 8 + 2 * t;
        *(float2*)(op0 + col) = make_float2(o[nd][0] * i0, o[nd][1] * i0);
        *(float2*)(op1 + col) = make_float2(o[nd][2] * i1, o[nd][3] * i1);
    }
}

// ---------------------------------------------------------------------------
extern "C" void kernel_launch(void* const* d_in, const int* in_sizes, int n_in,
                              void* d_out, int out_size)
{
    const float* query   = (const float*)d_in[0];
    const float* key_in  = (const float*)d_in[1];
    const float* value   = (const float*)d_in[2];
    const float* scaling = (const float*)d_in[3];
    const float* in_w    = (const float*)d_in[4];
    const float* in_b    = (const float*)d_in[5];
    const float* pn_w    = (const float*)d_in[6];
    const float* pn_b    = (const float*)d_in[7];
    const float* out_w   = (const float*)d_in[8];
    const float* out_b   = (const float*)d_in[9];
    float* out = (float*)d_out;

    // 1) QKV projections -> scratch in [n,h,len,d]
    dim3 gproj(ROWS / 128, EMB / 64, 3);
    gemm_mma_kernel<0><<<gproj, 256>>>(query, key_in, value, in_w, in_b, nullptr);

    // 2) LayerNorm K and V over D
    const int ln_rows = 2 * NB * NH * SK;
    ln_kernel<<<ln_rows / 8, 256>>>(pn_w, pn_b);

    // 3) Flash attention
    dim3 gattn(LQ / 64, NB * NH);
    attn_mma_kernel<<<gattn, 128>>>(scaling);

    // 4) Output projection -> d_out
    dim3 gout(ROWS / 128, EMB / 64, 1);
    gemm_mma_kernel<1><<<gout, 256>>>(nullptr, nullptr, nullptr, out_w, out_b, out);
}

// round 11
// speedup vs baseline: 1.8489x; 1.6092x over previous
#include <cuda_runtime.h>
#include <cuda_bf16.h>

#define LQ  2048
#define SK  2048
#define NB  4
#define EMB 512
#define NH  16
#define HD  32
#define ROWS (LQ * NB)   // 8192

// Scratch (allocation-free rule: __device__ globals)
__device__ float g_Q[NB * NH * LQ * HD];   // [n,h,l,d]
__device__ float g_K[NB * NH * SK * HD];   // [n,h,s,d]
__device__ float g_V[NB * NH * SK * HD];
__device__ float g_O[ROWS * EMB];          // attention output, (l*NB+n, e) row-major

// ---------------------------------------------------------------------------
// helpers
// ---------------------------------------------------------------------------
__device__ __forceinline__ void mma_bf16(float* c, const unsigned* a,
                                         unsigned b0, unsigned b1) {
    asm volatile(
        "mma.sync.aligned.m16n8k16.row.col.f32.bf16.bf16.f32 "
        "{%0,%1,%2,%3}, {%4,%5,%6,%7}, {%8,%9}, {%0,%1,%2,%3};"
        : "+f"(c[0]), "+f"(c[1]), "+f"(c[2]), "+f"(c[3])
        : "r"(a[0]), "r"(a[1]), "r"(a[2]), "r"(a[3]), "r"(b0), "r"(b1));
}
// split (x,y) into packed bf16x2 hi and lo words (x in low half)
__device__ __forceinline__ void bsplit2(float x, float y, unsigned &hi, unsigned &lo) {
    __nv_bfloat162 h = __floats2bfloat162_rn(x, y);
    const float hx = __bfloat162float(h.x);
    const float hy = __bfloat162float(h.y);
    __nv_bfloat162 l = __floats2bfloat162_rn(x - hx, y - hy);
    hi = *reinterpret_cast<unsigned*>(&h);
    lo = *reinterpret_cast<unsigned*>(&l);
}
// pack 8 consecutive floats (two float4) into hi/lo uint4 (8 bf16 each)
__device__ __forceinline__ void pack8(const float4 a, const float4 b,
                                      uint4 &hi, uint4 &lo) {
    bsplit2(a.x, a.y, hi.x, lo.x);
    bsplit2(a.z, a.w, hi.y, lo.y);
    bsplit2(b.x, b.y, hi.z, lo.z);
    bsplit2(b.z, b.w, hi.w, lo.w);
}
__device__ __forceinline__ void ldsm4(uint4 &d, unsigned addr) {
    asm volatile("ldmatrix.sync.aligned.m8n8.x4.shared.b16 {%0,%1,%2,%3}, [%4];"
                 : "=r"(d.x), "=r"(d.y), "=r"(d.z), "=r"(d.w) : "r"(addr));
}
__device__ __forceinline__ void ldsm4t(uint4 &d, unsigned addr) {
    asm volatile("ldmatrix.sync.aligned.m8n8.x4.trans.shared.b16 {%0,%1,%2,%3}, [%4];"
                 : "=r"(d.x), "=r"(d.y), "=r"(d.z), "=r"(d.w) : "r"(addr));
}
// swizzled uint4-index for a tile row: unit u (0..7) XORed with row&7
__device__ __forceinline__ int swz(int row, int u) {
    return row * 8 + (u ^ (row & 7));
}

// ---------------------------------------------------------------------------
// 3xBF16 tensor-core GEMM: out[r,f] = sum_e A[r,e] * W[f,e] + bias[f]
// Block tile 128x64, BK=32, 256 threads = 8 warps (4M x 2N), warptile 32x32.
// Smem row-major: each tile row = [hi 64B | lo 64B] (8 x 16B units, swizzled).
// STS.128 vectorized stores; fragments via ldmatrix.x4.
// ---------------------------------------------------------------------------
template<int MODE>
__global__ __launch_bounds__(256)
void gemm_mma_kernel(const float* __restrict__ Aq, const float* __restrict__ Ak,
                     const float* __restrict__ Av, const float* __restrict__ Wfull,
                     const float* __restrict__ bfull, float* __restrict__ outp)
{
    __shared__ uint4 ASm[128 * 8];   // 16KB
    __shared__ uint4 BSm[64 * 8];    //  8KB

    const int tid    = threadIdx.x;
    const int warp   = tid >> 5;
    const int lane   = tid & 31;
    const int g      = lane >> 2;
    const int t      = lane & 3;
    const int warp_m = warp >> 1;   // 0..3
    const int warp_n = warp & 1;    // 0..1
    const int r0     = blockIdx.x * 128;
    const int f0     = blockIdx.y * 64;

    const float* A;
    const float* W;
    const float* bias;
    if (MODE == 0) {
        const int z = blockIdx.z;
        A    = (z == 0) ? Aq : (z == 1) ? Ak : Av;
        W    = Wfull + z * EMB * EMB;
        bias = bfull + z * EMB;
    } else {
        A    = g_O;
        W    = Wfull;
        bias = bfull;
    }

    const int rowA = tid >> 1;           // 0..127
    const int colA = (tid & 1) * 16;     // 0 or 16
    const int rowB = tid >> 2;           // 0..63
    const int colB = (tid & 3) * 8;      // 0,8,16,24

    const unsigned aBase = (unsigned)__cvta_generic_to_shared(ASm);
    const unsigned bBase = (unsigned)__cvta_generic_to_shared(BSm);
    const int lm = lane >> 3;            // ldmatrix matrix index
    const int lr = lane & 7;             // row within matrix

    float acc[2][4][4];
    #pragma unroll
    for (int mi = 0; mi < 2; mi++)
        #pragma unroll
        for (int ni = 0; ni < 4; ni++)
            #pragma unroll
            for (int j = 0; j < 4; j++) acc[mi][ni][j] = 0.f;

    // initial global prefetch
    float4 aR[4], bR[2];
    #pragma unroll
    for (int i = 0; i < 4; i++)
        aR[i] = *(const float4*)(A + (size_t)(r0 + rowA) * EMB + colA + i * 4);
    #pragma unroll
    for (int i = 0; i < 2; i++)
        bR[i] = *(const float4*)(W + (size_t)(f0 + rowB) * EMB + colB + i * 4);

    for (int k0 = 0; k0 < EMB; k0 += 32) {
        // ---- vectorized store of prefetched tile (bf16 hi/lo) ----
        {
            uint4 hi, lo;
            int u = colA >> 3;
            pack8(aR[0], aR[1], hi, lo);
            ASm[swz(rowA, u)]     = hi;
            ASm[swz(rowA, u + 4)] = lo;
            pack8(aR[2], aR[3], hi, lo);
            ASm[swz(rowA, u + 1)] = hi;
            ASm[swz(rowA, u + 5)] = lo;
            pack8(bR[0], bR[1], hi, lo);
            int ub = colB >> 3;
            BSm[swz(rowB, ub)]     = hi;
            BSm[swz(rowB, ub + 4)] = lo;
        }
        __syncthreads();

        // ---- issue next global loads (overlap with compute) ----
        if (k0 + 32 < EMB) {
            #pragma unroll
            for (int i = 0; i < 4; i++)
                aR[i] = *(const float4*)(A + (size_t)(r0 + rowA) * EMB + k0 + 32 + colA + i * 4);
            #pragma unroll
            for (int i = 0; i < 2; i++)
                bR[i] = *(const float4*)(W + (size_t)(f0 + rowB) * EMB + k0 + 32 + colB + i * 4);
        }

        // ---- compute: 2 k16-steps ----
        #pragma unroll
        for (int ks = 0; ks < 2; ks++) {
            uint4 ah[2], al[2], bh[2], bl[2];
            #pragma unroll
            for (int mi = 0; mi < 2; mi++) {
                const int row = warp_m * 32 + mi * 16 + ((lm & 1) << 3) + lr;
                const int u   = ks * 2 + (lm >> 1);
                ldsm4(ah[mi], aBase + swz(row, u) * 16);
                ldsm4(al[mi], aBase + swz(row, u + 4) * 16);
            }
            #pragma unroll
            for (int bi = 0; bi < 2; bi++) {
                const int row = warp_n * 32 + bi * 16 + ((lm >> 1) << 3) + lr;
                const int u   = ks * 2 + (lm & 1);
                ldsm4(bh[bi], bBase + swz(row, u) * 16);
                ldsm4(bl[bi], bBase + swz(row, u + 4) * 16);
            }
            #pragma unroll
            for (int ni = 0; ni < 4; ni++) {
                const int bi = ni >> 1;
                const unsigned h0 = (ni & 1) ? bh[bi].z : bh[bi].x;
                const unsigned h1 = (ni & 1) ? bh[bi].w : bh[bi].y;
                const unsigned l0 = (ni & 1) ? bl[bi].z : bl[bi].x;
                const unsigned l1 = (ni & 1) ? bl[bi].w : bl[bi].y;
                #pragma unroll
                for (int mi = 0; mi < 2; mi++) {
                    mma_bf16(acc[mi][ni], &ah[mi].x, h0, h1);
                    mma_bf16(acc[mi][ni], &ah[mi].x, l0, l1);
                    mma_bf16(acc[mi][ni], &al[mi].x, h0, h1);
                }
            }
        }
        __syncthreads();
    }

    // ---- epilogue: c0=(g,2t) c1=(g,2t+1) c2=(g+8,2t) c3=(g+8,2t+1) ----
    #pragma unroll
    for (int mi = 0; mi < 2; mi++) {
        const int rA = r0 + warp_m * 32 + mi * 16 + g;
        const int rB = rA + 8;
        #pragma unroll
        for (int ni = 0; ni < 4; ni++) {
            const float* c = acc[mi][ni];
            const int f  = f0 + warp_n * 32 + ni * 8 + 2 * t;
            const float b0 = bias[f];
            const float b1 = bias[f + 1];
            if (MODE == 0) {
                float* dst = (blockIdx.z == 0) ? g_Q : (blockIdx.z == 1) ? g_K : g_V;
                const int h = f >> 5;
                const int d = f & 31;
                {
                    const int l = rA >> 2, n = rA & 3;
                    *(float2*)(dst + ((size_t)(n * NH + h) * LQ + l) * HD + d) =
                        make_float2(c[0] + b0, c[1] + b1);
                }
                {
                    const int l = rB >> 2, n = rB & 3;
                    *(float2*)(dst + ((size_t)(n * NH + h) * LQ + l) * HD + d) =
                        make_float2(c[2] + b0, c[3] + b1);
                }
            } else {
                *(float2*)(outp + (size_t)rA * EMB + f) = make_float2(c[0] + b0, c[1] + b1);
                *(float2*)(outp + (size_t)rB * EMB + f) = make_float2(c[2] + b0, c[3] + b1);
            }
        }
    }
}

// ---------------------------------------------------------------------------
// LayerNorm over D=32 for K and V (one warp per row)
// ---------------------------------------------------------------------------
__global__ __launch_bounds__(256)
void ln_kernel(const float* __restrict__ w, const float* __restrict__ b)
{
    const int gw   = (blockIdx.x * blockDim.x + threadIdx.x) >> 5;
    const int lane = threadIdx.x & 31;
    const int R    = NB * NH * SK;
    if (gw >= 2 * R) return;
    float* X      = (gw < R) ? g_K : g_V;
    const int row = (gw < R) ? gw : gw - R;

    float x = X[(size_t)row * HD + lane];
    float s = x;
    #pragma unroll
    for (int o = 16; o; o >>= 1) s += __shfl_xor_sync(0xffffffffu, s, o);
    const float mu = s * (1.0f / HD);
    const float dv = x - mu;
    float vv = dv * dv;
    #pragma unroll
    for (int o = 16; o; o >>= 1) vv += __shfl_xor_sync(0xffffffffu, vv, o);
    const float inv = rsqrtf(vv * (1.0f / HD) + 1e-5f);
    X[(size_t)row * HD + lane] = dv * inv * w[lane] + b[lane];
}

// ---------------------------------------------------------------------------
// Flash attention, all-bf16 compensated:
//   QK = Qh*Kh + Qh*Kl + Ql*Kh   (fp32-level scores)
//   PV = Ph*Vh + Ph*Vl + Pl*Vh   (fp32-level output; P C-frag repacks to
//        A-frag with plain cvt — NO shuffles — and V comes via ldmatrix.trans)
// Block 128 thr (4 warps), 16 q rows/warp, S-chunks of 64.
// K and V in row-major [hi|lo] swizzled smem, vectorized STS.128.
// Q pre-scaled by beta*log2(e); softmax in exp2 domain.
// ---------------------------------------------------------------------------
__global__ __launch_bounds__(128)
void attn_mma_kernel(const float* __restrict__ scaling)
{
    __shared__ uint4 KSm[64 * 8];   // 8KB
    __shared__ uint4 VSm[64 * 8];   // 8KB

    const int tid  = threadIdx.x;
    const int warp = tid >> 5;
    const int lane = tid & 31;
    const int g    = lane >> 2;
    const int t    = lane & 3;
    const int nh   = blockIdx.y;   // n*NH + h
    const int h    = nh & (NH - 1);
    const float betaL = scaling[h] * 1.4426950408889634f;
    const int q0   = blockIdx.x * 64 + warp * 16;

    const unsigned kBase = (unsigned)__cvta_generic_to_shared(KSm);
    const unsigned vBase = (unsigned)__cvta_generic_to_shared(VSm);
    const int lm = lane >> 3;
    const int lr = lane & 7;

    // Q fragments: 2 k16-steps over D=32, bf16 hi/lo split, beta*log2e folded
    const float* Qp = g_Q + ((size_t)nh * LQ + q0) * HD;
    unsigned aqh[2][4], aql[2][4];
    #pragma unroll
    for (int ks = 0; ks < 2; ks++) {
        const int c0 = ks * 16 + 2 * t;
        const int c2 = c0 + 8;
        bsplit2(Qp[(size_t)g       * HD + c0] * betaL, Qp[(size_t)g       * HD + c0 + 1] * betaL,
                aqh[ks][0], aql[ks][0]);
        bsplit2(Qp[(size_t)(g + 8) * HD + c0] * betaL, Qp[(size_t)(g + 8) * HD + c0 + 1] * betaL,
                aqh[ks][1], aql[ks][1]);
        bsplit2(Qp[(size_t)g       * HD + c2] * betaL, Qp[(size_t)g       * HD + c2 + 1] * betaL,
                aqh[ks][2], aql[ks][2]);
        bsplit2(Qp[(size_t)(g + 8) * HD + c2] * betaL, Qp[(size_t)(g + 8) * HD + c2 + 1] * betaL,
                aqh[ks][3], aql[ks][3]);
    }

    float m0 = -1e30f, m1 = -1e30f, l0 = 0.f, l1 = 0.f;
    float o[4][4];
    #pragma unroll
    for (int nd = 0; nd < 4; nd++)
        #pragma unroll
        for (int j = 0; j < 4; j++) o[nd][j] = 0.f;

    const float* Kb = g_K + (size_t)nh * SK * HD;
    const float* Vb = g_V + (size_t)nh * SK * HD;
    const int rowL = tid >> 1;           // 0..63
    const int colL = (tid & 1) * 16;     // 0 or 16

    for (int s0 = 0; s0 < SK; s0 += 64) {
        // ---- cooperative vectorized load of K and V (hi/lo bf16) ----
        {
            const float* Kr = Kb + (size_t)(s0 + rowL) * HD + colL;
            const float* Vr = Vb + (size_t)(s0 + rowL) * HD + colL;
            const int u = colL >> 3;
            uint4 hi, lo;
            pack8(*(const float4*)(Kr),     *(const float4*)(Kr + 4),  hi, lo);
            KSm[swz(rowL, u)]     = hi;
            KSm[swz(rowL, u + 4)] = lo;
            pack8(*(const float4*)(Kr + 8), *(const float4*)(Kr + 12), hi, lo);
            KSm[swz(rowL, u + 1)] = hi;
            KSm[swz(rowL, u + 5)] = lo;
            pack8(*(const float4*)(Vr),     *(const float4*)(Vr + 4),  hi, lo);
            VSm[swz(rowL, u)]     = hi;
            VSm[swz(rowL, u + 4)] = lo;
            pack8(*(const float4*)(Vr + 8), *(const float4*)(Vr + 12), hi, lo);
            VSm[swz(rowL, u + 1)] = hi;
            VSm[swz(rowL, u + 5)] = lo;
        }
        __syncthreads();

        // ---- QK scores (3xBF16): 8 s-tiles of 16x8 ----
        float sc[8][4];
        #pragma unroll
        for (int nd = 0; nd < 8; nd++) {
            sc[nd][0] = sc[nd][1] = sc[nd][2] = sc[nd][3] = 0.f;
            const int row = nd * 8 + lr;
            uint4 kh, kl;
            ldsm4(kh, kBase + swz(row, lm) * 16);
            ldsm4(kl, kBase + swz(row, lm + 4) * 16);
            mma_bf16(sc[nd], aqh[0], kh.x, kh.y);
            mma_bf16(sc[nd], aqh[1], kh.z, kh.w);
            mma_bf16(sc[nd], aqh[0], kl.x, kl.y);
            mma_bf16(sc[nd], aqh[1], kl.z, kl.w);
            mma_bf16(sc[nd], aql[0], kh.x, kh.y);
            mma_bf16(sc[nd], aql[1], kh.z, kh.w);
        }

        // ---- online softmax (exp2 domain) ----
        float t0 = -1e30f, t1 = -1e30f;
        #pragma unroll
        for (int nd = 0; nd < 8; nd++) {
            t0 = fmaxf(t0, fmaxf(sc[nd][0], sc[nd][1]));
            t1 = fmaxf(t1, fmaxf(sc[nd][2], sc[nd][3]));
        }
        t0 = fmaxf(t0, __shfl_xor_sync(0xffffffffu, t0, 1));
        t0 = fmaxf(t0, __shfl_xor_sync(0xffffffffu, t0, 2));
        t1 = fmaxf(t1, __shfl_xor_sync(0xffffffffu, t1, 1));
        t1 = fmaxf(t1, __shfl_xor_sync(0xffffffffu, t1, 2));

        const float nm0 = fmaxf(m0, t0);
        const float nm1 = fmaxf(m1, t1);
        const float c0  = exp2f(m0 - nm0);
        const float c1  = exp2f(m1 - nm1);

        float rs0 = 0.f, rs1 = 0.f;
        #pragma unroll
        for (int nd = 0; nd < 8; nd++) {
            sc[nd][0] = exp2f(sc[nd][0] - nm0);
            sc[nd][1] = exp2f(sc[nd][1] - nm0);
            sc[nd][2] = exp2f(sc[nd][2] - nm1);
            sc[nd][3] = exp2f(sc[nd][3] - nm1);
            rs0 += sc[nd][0] + sc[nd][1];
            rs1 += sc[nd][2] + sc[nd][3];
        }
        rs0 += __shfl_xor_sync(0xffffffffu, rs0, 1);
        rs0 += __shfl_xor_sync(0xffffffffu, rs0, 2);
        rs1 += __shfl_xor_sync(0xffffffffu, rs1, 1);
        rs1 += __shfl_xor_sync(0xffffffffu, rs1, 2);

        l0 = l0 * c0 + rs0;
        l1 = l1 * c1 + rs1;
        #pragma unroll
        for (int nd = 0; nd < 4; nd++) {
            o[nd][0] *= c0; o[nd][1] *= c0;
            o[nd][2] *= c1; o[nd][3] *= c1;
        }
        m0 = nm0; m1 = nm1;

        // ---- PV (3xBF16): P repacked directly (no shuffles), V via trans ----
        #pragma unroll
        for (int kb = 0; kb < 4; kb++) {
            unsigned ph[4], pl[4];
            bsplit2(sc[2 * kb][0],     sc[2 * kb][1],     ph[0], pl[0]);
            bsplit2(sc[2 * kb][2],     sc[2 * kb][3],     ph[1], pl[1]);
            bsplit2(sc[2 * kb + 1][0], sc[2 * kb + 1][1], ph[2], pl[2]);
            bsplit2(sc[2 * kb + 1][2], sc[2 * kb + 1][3], ph[3], pl[3]);
            #pragma unroll
            for (int dp = 0; dp < 2; dp++) {
                const int row = kb * 16 + ((lm & 1) << 3) + lr;
                const int u   = dp * 2 + (lm >> 1);
                uint4 vh, vl;
                ldsm4t(vh, vBase + swz(row, u) * 16);
                ldsm4t(vl, vBase + swz(row, u + 4) * 16);
                mma_bf16(o[2 * dp],     ph, vh.x, vh.y);
                mma_bf16(o[2 * dp],     ph, vl.x, vl.y);
                mma_bf16(o[2 * dp],     pl, vh.x, vh.y);
                mma_bf16(o[2 * dp + 1], ph, vh.z, vh.w);
                mma_bf16(o[2 * dp + 1], ph, vl.z, vl.w);
                mma_bf16(o[2 * dp + 1], pl, vh.z, vh.w);
            }
        }
        __syncthreads();
    }

    // ---- epilogue ----
    const float i0 = 1.0f / l0;
    const float i1 = 1.0f / l1;
    const int n = nh >> 4;
    float* op0 = g_O + ((size_t)(q0 + g)     * NB + n) * EMB + h * HD;
    float* op1 = g_O + ((size_t)(q0 + g + 8) * NB + n) * EMB + h * HD;
    #pragma unroll
    for (int nd = 0; nd < 4; nd++) {
        const int col = nd * 8 + 2 * t;
        *(float2*)(op0 + col) = make_float2(o[nd][0] * i0, o[nd][1] * i0);
        *(float2*)(op1 + col) = make_float2(o[nd][2] * i1, o[nd][3] * i1);
    }
}

// ---------------------------------------------------------------------------
extern "C" void kernel_launch(void* const* d_in, const int* in_sizes, int n_in,
                              void* d_out, int out_size)
{
    const float* query   = (const float*)d_in[0];
    const float* key_in  = (const float*)d_in[1];
    const float* value   = (const float*)d_in[2];
    const float* scaling = (const float*)d_in[3];
    const float* in_w    = (const float*)d_in[4];
    const float* in_b    = (const float*)d_in[5];
    const float* pn_w    = (const float*)d_in[6];
    const float* pn_b    = (const float*)d_in[7];
    const float* out_w   = (const float*)d_in[8];
    const float* out_b   = (const float*)d_in[9];
    float* out = (float*)d_out;

    // 1) QKV projections -> scratch in [n,h,len,d]
    dim3 gproj(ROWS / 128, EMB / 64, 3);
    gemm_mma_kernel<0><<<gproj, 256>>>(query, key_in, value, in_w, in_b, nullptr);

    // 2) LayerNorm K and V over D
    const int ln_rows = 2 * NB * NH * SK;
    ln_kernel<<<ln_rows / 8, 256>>>(pn_w, pn_b);

    // 3) Flash attention
    dim3 gattn(LQ / 64, NB * NH);
    attn_mma_kernel<<<gattn, 128>>>(scaling);

    // 4) Output projection -> d_out
    dim3 gout(ROWS / 128, EMB / 64, 1);
    gemm_mma_kernel<1><<<gout, 256>>>(nullptr, nullptr, nullptr, out_w, out_b, out);
}

// round 13
// speedup vs baseline: 1.9515x; 1.0554x over previous
#include <cuda_runtime.h>
#include <cuda_bf16.h>

#define LQ  2048
#define SK  2048
#define NB  4
#define EMB 512
#define NH  16
#define HD  32
#define ROWS (LQ * NB)   // 8192

// Scratch (allocation-free rule: __device__ globals)
__device__ float g_Q[NB * NH * LQ * HD];   // [n,h,l,d]
__device__ float g_K[NB * NH * SK * HD];   // [n,h,s,d]  (LayerNorm fused in proj)
__device__ float g_V[NB * NH * SK * HD];
__device__ float g_O[ROWS * EMB];          // attention output, (l*NB+n, e) row-major

// ---------------------------------------------------------------------------
// helpers
// ---------------------------------------------------------------------------
__device__ __forceinline__ void mma_bf16(float* c, const unsigned* a,
                                         unsigned b0, unsigned b1) {
    asm volatile(
        "mma.sync.aligned.m16n8k16.row.col.f32.bf16.bf16.f32 "
        "{%0,%1,%2,%3}, {%4,%5,%6,%7}, {%8,%9}, {%0,%1,%2,%3};"
        : "+f"(c[0]), "+f"(c[1]), "+f"(c[2]), "+f"(c[3])
        : "r"(a[0]), "r"(a[1]), "r"(a[2]), "r"(a[3]), "r"(b0), "r"(b1));
}
__device__ __forceinline__ void bsplit2(float x, float y, unsigned &hi, unsigned &lo) {
    __nv_bfloat162 h = __floats2bfloat162_rn(x, y);
    const float hx = __bfloat162float(h.x);
    const float hy = __bfloat162float(h.y);
    __nv_bfloat162 l = __floats2bfloat162_rn(x - hx, y - hy);
    hi = *reinterpret_cast<unsigned*>(&h);
    lo = *reinterpret_cast<unsigned*>(&l);
}
__device__ __forceinline__ void pack8(const float4 a, const float4 b,
                                      uint4 &hi, uint4 &lo) {
    bsplit2(a.x, a.y, hi.x, lo.x);
    bsplit2(a.z, a.w, hi.y, lo.y);
    bsplit2(b.x, b.y, hi.z, lo.z);
    bsplit2(b.z, b.w, hi.w, lo.w);
}
__device__ __forceinline__ void ldsm4(uint4 &d, unsigned addr) {
    asm volatile("ldmatrix.sync.aligned.m8n8.x4.shared.b16 {%0,%1,%2,%3}, [%4];"
                 : "=r"(d.x), "=r"(d.y), "=r"(d.z), "=r"(d.w) : "r"(addr));
}
__device__ __forceinline__ void ldsm4t(uint4 &d, unsigned addr) {
    asm volatile("ldmatrix.sync.aligned.m8n8.x4.trans.shared.b16 {%0,%1,%2,%3}, [%4];"
                 : "=r"(d.x), "=r"(d.y), "=r"(d.z), "=r"(d.w) : "r"(addr));
}
__device__ __forceinline__ int swz(int row, int u) {
    return row * 8 + (u ^ (row & 7));
}
__device__ __forceinline__ float ex2f(float x) {
    float y;
    asm("ex2.approx.ftz.f32 %0, %1;" : "=f"(y) : "f"(x));
    return y;
}

// ---------------------------------------------------------------------------
// 3xBF16 tensor-core GEMM: out[r,f] = sum_e A[r,e] * W[f,e] + bias[f]
// Block tile 128x64, BK=32, 256 threads = 8 warps (4M x 2N), warptile 32x32.
// MODE 0 additionally applies LayerNorm over the head dim (D=32) for K and V
// (blockIdx.z = 1,2) in the epilogue — the quad (t=0..3) of a row holds the
// full 32-wide head slice, so LN is 4 shuffles + rsqrt.
// ---------------------------------------------------------------------------
template<int MODE>
__global__ __launch_bounds__(256)
void gemm_mma_kernel(const float* __restrict__ Aq, const float* __restrict__ Ak,
                     const float* __restrict__ Av, const float* __restrict__ Wfull,
                     const float* __restrict__ bfull, float* __restrict__ outp,
                     const float* __restrict__ pnw, const float* __restrict__ pnb)
{
    __shared__ uint4 ASm[128 * 8];   // 16KB
    __shared__ uint4 BSm[64 * 8];    //  8KB

    const int tid    = threadIdx.x;
    const int warp   = tid >> 5;
    const int lane   = tid & 31;
    const int g      = lane >> 2;
    const int t      = lane & 3;
    const int warp_m = warp >> 1;   // 0..3
    const int warp_n = warp & 1;    // 0..1
    const int r0     = blockIdx.x * 128;
    const int f0     = blockIdx.y * 64;

    const float* A;
    const float* W;
    const float* bias;
    if (MODE == 0) {
        const int z = blockIdx.z;
        A    = (z == 0) ? Aq : (z == 1) ? Ak : Av;
        W    = Wfull + z * EMB * EMB;
        bias = bfull + z * EMB;
    } else {
        A    = g_O;
        W    = Wfull;
        bias = bfull;
    }

    const int rowA = tid >> 1;           // 0..127
    const int colA = (tid & 1) * 16;     // 0 or 16
    const int rowB = tid >> 2;           // 0..63
    const int colB = (tid & 3) * 8;      // 0,8,16,24

    const unsigned aBase = (unsigned)__cvta_generic_to_shared(ASm);
    const unsigned bBase = (unsigned)__cvta_generic_to_shared(BSm);
    const int lm = lane >> 3;            // ldmatrix matrix index
    const int lr = lane & 7;             // row within matrix

    float acc[2][4][4];
    #pragma unroll
    for (int mi = 0; mi < 2; mi++)
        #pragma unroll
        for (int ni = 0; ni < 4; ni++)
            #pragma unroll
            for (int j = 0; j < 4; j++) acc[mi][ni][j] = 0.f;

    // initial global prefetch
    float4 aR[4], bR[2];
    #pragma unroll
    for (int i = 0; i < 4; i++)
        aR[i] = *(const float4*)(A + (size_t)(r0 + rowA) * EMB + colA + i * 4);
    #pragma unroll
    for (int i = 0; i < 2; i++)
        bR[i] = *(const float4*)(W + (size_t)(f0 + rowB) * EMB + colB + i * 4);

    for (int k0 = 0; k0 < EMB; k0 += 32) {
        // ---- vectorized store of prefetched tile (bf16 hi/lo) ----
        {
            uint4 hi, lo;
            int u = colA >> 3;
            pack8(aR[0], aR[1], hi, lo);
            ASm[swz(rowA, u)]     = hi;
            ASm[swz(rowA, u + 4)] = lo;
            pack8(aR[2], aR[3], hi, lo);
            ASm[swz(rowA, u + 1)] = hi;
            ASm[swz(rowA, u + 5)] = lo;
            pack8(bR[0], bR[1], hi, lo);
            int ub = colB >> 3;
            BSm[swz(rowB, ub)]     = hi;
            BSm[swz(rowB, ub + 4)] = lo;
        }
        __syncthreads();

        // ---- issue next global loads (overlap with compute) ----
        if (k0 + 32 < EMB) {
            #pragma unroll
            for (int i = 0; i < 4; i++)
                aR[i] = *(const float4*)(A + (size_t)(r0 + rowA) * EMB + k0 + 32 + colA + i * 4);
            #pragma unroll
            for (int i = 0; i < 2; i++)
                bR[i] = *(const float4*)(W + (size_t)(f0 + rowB) * EMB + k0 + 32 + colB + i * 4);
        }

        // ---- compute: 2 k16-steps ----
        #pragma unroll
        for (int ks = 0; ks < 2; ks++) {
            uint4 ah[2], al[2], bh[2], bl[2];
            #pragma unroll
            for (int mi = 0; mi < 2; mi++) {
                const int row = warp_m * 32 + mi * 16 + ((lm & 1) << 3) + lr;
                const int u   = ks * 2 + (lm >> 1);
                ldsm4(ah[mi], aBase + swz(row, u) * 16);
                ldsm4(al[mi], aBase + swz(row, u + 4) * 16);
            }
            #pragma unroll
            for (int bi = 0; bi < 2; bi++) {
                const int row = warp_n * 32 + bi * 16 + ((lm >> 1) << 3) + lr;
                const int u   = ks * 2 + (lm & 1);
                ldsm4(bh[bi], bBase + swz(row, u) * 16);
                ldsm4(bl[bi], bBase + swz(row, u + 4) * 16);
            }
            #pragma unroll
            for (int ni = 0; ni < 4; ni++) {
                const int bi = ni >> 1;
                const unsigned h0 = (ni & 1) ? bh[bi].z : bh[bi].x;
                const unsigned h1 = (ni & 1) ? bh[bi].w : bh[bi].y;
                const unsigned l0 = (ni & 1) ? bl[bi].z : bl[bi].x;
                const unsigned l1 = (ni & 1) ? bl[bi].w : bl[bi].y;
                #pragma unroll
                for (int mi = 0; mi < 2; mi++) {
                    mma_bf16(acc[mi][ni], &ah[mi].x, h0, h1);
                    mma_bf16(acc[mi][ni], &ah[mi].x, l0, l1);
                    mma_bf16(acc[mi][ni], &al[mi].x, h0, h1);
                }
            }
        }
        __syncthreads();
    }

    // ---- epilogue ----
    // c0=(g,2t) c1=(g,2t+1) c2=(g+8,2t) c3=(g+8,2t+1)
    if (MODE == 0) {
        float* dst = (blockIdx.z == 0) ? g_Q : (blockIdx.z == 1) ? g_K : g_V;
        const bool doLN = (blockIdx.z != 0);
        // per-thread head-dim slice: d = ni*8 + 2t (+1)
        float pwv[8], pbv[8];
        if (doLN) {
            #pragma unroll
            for (int ni = 0; ni < 4; ni++) {
                const int d = ni * 8 + 2 * t;
                pwv[ni * 2 + 0] = pnw[d];
                pwv[ni * 2 + 1] = pnw[d + 1];
                pbv[ni * 2 + 0] = pnb[d];
                pbv[ni * 2 + 1] = pnb[d + 1];
            }
        }
        #pragma unroll
        for (int mi = 0; mi < 2; mi++) {
            float vals[2][8];
            #pragma unroll
            for (int ni = 0; ni < 4; ni++) {
                const int f = f0 + warp_n * 32 + ni * 8 + 2 * t;
                const float b0 = bias[f];
                const float b1 = bias[f + 1];
                vals[0][ni * 2 + 0] = acc[mi][ni][0] + b0;
                vals[0][ni * 2 + 1] = acc[mi][ni][1] + b1;
                vals[1][ni * 2 + 0] = acc[mi][ni][2] + b0;
                vals[1][ni * 2 + 1] = acc[mi][ni][3] + b1;
            }
            if (doLN) {
                #pragma unroll
                for (int rh = 0; rh < 2; rh++) {
                    float s = 0.f, s2 = 0.f;
                    #pragma unroll
                    for (int j = 0; j < 8; j++) {
                        s  += vals[rh][j];
                        s2 += vals[rh][j] * vals[rh][j];
                    }
                    s  += __shfl_xor_sync(0xffffffffu, s, 1);
                    s  += __shfl_xor_sync(0xffffffffu, s, 2);
                    s2 += __shfl_xor_sync(0xffffffffu, s2, 1);
                    s2 += __shfl_xor_sync(0xffffffffu, s2, 2);
                    const float mu  = s * (1.0f / HD);
                    const float var = s2 * (1.0f / HD) - mu * mu;
                    const float inv = rsqrtf(var + 1e-5f);
                    #pragma unroll
                    for (int j = 0; j < 8; j++)
                        vals[rh][j] = (vals[rh][j] - mu) * inv * pwv[j] + pbv[j];
                }
            }
            const int rA = r0 + warp_m * 32 + mi * 16 + g;
            const int h  = (f0 + warp_n * 32) >> 5;
            #pragma unroll
            for (int rh = 0; rh < 2; rh++) {
                const int r = rA + rh * 8;
                const int l = r >> 2, n = r & 3;
                float* p = dst + ((size_t)(n * NH + h) * LQ + l) * HD;
                #pragma unroll
                for (int ni = 0; ni < 4; ni++) {
                    const int d = ni * 8 + 2 * t;
                    *(float2*)(p + d) = make_float2(vals[rh][ni * 2], vals[rh][ni * 2 + 1]);
                }
            }
        }
    } else {
        #pragma unroll
        for (int mi = 0; mi < 2; mi++) {
            const int rA = r0 + warp_m * 32 + mi * 16 + g;
            const int rB = rA + 8;
            #pragma unroll
            for (int ni = 0; ni < 4; ni++) {
                const float* c = acc[mi][ni];
                const int f  = f0 + warp_n * 32 + ni * 8 + 2 * t;
                const float b0 = bias[f];
                const float b1 = bias[f + 1];
                *(float2*)(outp + (size_t)rA * EMB + f) = make_float2(c[0] + b0, c[1] + b1);
                *(float2*)(outp + (size_t)rB * EMB + f) = make_float2(c[2] + b0, c[3] + b1);
            }
        }
    }
}

// ---------------------------------------------------------------------------
// Flash attention, all-bf16 compensated (QK and PV = hi*hi + hi*lo + lo*hi).
// Block 256 thr (8 warps), 16 q rows/warp -> 128 q rows per block.
// S-chunks of 64; K/V register-prefetched, then packed to swizzled smem.
// Q pre-scaled by beta*log2(e); softmax via ex2.approx.
// ---------------------------------------------------------------------------
__global__ __launch_bounds__(256)
void attn_mma_kernel(const float* __restrict__ scaling)
{
    __shared__ uint4 KSm[64 * 8];   // 8KB
    __shared__ uint4 VSm[64 * 8];   // 8KB

    const int tid  = threadIdx.x;
    const int warp = tid >> 5;
    const int lane = tid & 31;
    const int g    = lane >> 2;
    const int t    = lane & 3;
    const int nh   = blockIdx.y;   // n*NH + h
    const int h    = nh & (NH - 1);
    const float betaL = scaling[h] * 1.4426950408889634f;
    const int q0   = blockIdx.x * 128 + warp * 16;

    const unsigned kBase = (unsigned)__cvta_generic_to_shared(KSm);
    const unsigned vBase = (unsigned)__cvta_generic_to_shared(VSm);
    const int lm = lane >> 3;
    const int lr = lane & 7;

    // Q fragments: 2 k16-steps over D=32, bf16 hi/lo split, beta*log2e folded
    const float* Qp = g_Q + ((size_t)nh * LQ + q0) * HD;
    unsigned aqh[2][4], aql[2][4];
    #pragma unroll
    for (int ks = 0; ks < 2; ks++) {
        const int c0 = ks * 16 + 2 * t;
        const int c2 = c0 + 8;
        bsplit2(Qp[(size_t)g       * HD + c0] * betaL, Qp[(size_t)g       * HD + c0 + 1] * betaL,
                aqh[ks][0], aql[ks][0]);
        bsplit2(Qp[(size_t)(g + 8) * HD + c0] * betaL, Qp[(size_t)(g + 8) * HD + c0 + 1] * betaL,
                aqh[ks][1], aql[ks][1]);
        bsplit2(Qp[(size_t)g       * HD + c2] * betaL, Qp[(size_t)g       * HD + c2 + 1] * betaL,
                aqh[ks][2], aql[ks][2]);
        bsplit2(Qp[(size_t)(g + 8) * HD + c2] * betaL, Qp[(size_t)(g + 8) * HD + c2 + 1] * betaL,
                aqh[ks][3], aql[ks][3]);
    }

    float m0 = -1e30f, m1 = -1e30f, l0 = 0.f, l1 = 0.f;
    float o[4][4];
    #pragma unroll
    for (int nd = 0; nd < 4; nd++)
        #pragma unroll
        for (int j = 0; j < 4; j++) o[nd][j] = 0.f;

    const float* Kb = g_K + (size_t)nh * SK * HD;
    const float* Vb = g_V + (size_t)nh * SK * HD;
    const int rowL = tid >> 2;           // 0..63
    const int colL = (tid & 3) * 8;      // 0,8,16,24
    const int uL   = colL >> 3;          // 0..3

    // register prefetch of chunk 0
    float4 kR[2], vR[2];
    {
        const float* Kr = Kb + (size_t)rowL * HD + colL;
        const float* Vr = Vb + (size_t)rowL * HD + colL;
        kR[0] = *(const float4*)(Kr);
        kR[1] = *(const float4*)(Kr + 4);
        vR[0] = *(const float4*)(Vr);
        vR[1] = *(const float4*)(Vr + 4);
    }

    for (int s0 = 0; s0 < SK; s0 += 64) {
        // ---- store prefetched K/V chunk to swizzled smem ----
        {
            uint4 hi, lo;
            pack8(kR[0], kR[1], hi, lo);
            KSm[swz(rowL, uL)]     = hi;
            KSm[swz(rowL, uL + 4)] = lo;
            pack8(vR[0], vR[1], hi, lo);
            VSm[swz(rowL, uL)]     = hi;
            VSm[swz(rowL, uL + 4)] = lo;
        }
        __syncthreads();

        // ---- prefetch next chunk (LDG latency hidden by compute) ----
        if (s0 + 64 < SK) {
            const float* Kr = Kb + (size_t)(s0 + 64 + rowL) * HD + colL;
            const float* Vr = Vb + (size_t)(s0 + 64 + rowL) * HD + colL;
            kR[0] = *(const float4*)(Kr);
            kR[1] = *(const float4*)(Kr + 4);
            vR[0] = *(const float4*)(Vr);
            vR[1] = *(const float4*)(Vr + 4);
        }

        // ---- QK scores (3xBF16): 8 s-tiles of 16x8 ----
        float sc[8][4];
        #pragma unroll
        for (int nd = 0; nd < 8; nd++) {
            sc[nd][0] = sc[nd][1] = sc[nd][2] = sc[nd][3] = 0.f;
            const int row = nd * 8 + lr;
            uint4 kh, kl;
            ldsm4(kh, kBase + swz(row, lm) * 16);
            ldsm4(kl, kBase + swz(row, lm + 4) * 16);
            mma_bf16(sc[nd], aqh[0], kh.x, kh.y);
            mma_bf16(sc[nd], aqh[1], kh.z, kh.w);
            mma_bf16(sc[nd], aqh[0], kl.x, kl.y);
            mma_bf16(sc[nd], aqh[1], kl.z, kl.w);
            mma_bf16(sc[nd], aql[0], kh.x, kh.y);
            mma_bf16(sc[nd], aql[1], kh.z, kh.w);
        }

        // ---- online softmax (exp2 domain, ex2.approx) ----
        float t0 = -1e30f, t1 = -1e30f;
        #pragma unroll
        for (int nd = 0; nd < 8; nd++) {
            t0 = fmaxf(t0, fmaxf(sc[nd][0], sc[nd][1]));
            t1 = fmaxf(t1, fmaxf(sc[nd][2], sc[nd][3]));
        }
        t0 = fmaxf(t0, __shfl_xor_sync(0xffffffffu, t0, 1));
        t0 = fmaxf(t0, __shfl_xor_sync(0xffffffffu, t0, 2));
        t1 = fmaxf(t1, __shfl_xor_sync(0xffffffffu, t1, 1));
        t1 = fmaxf(t1, __shfl_xor_sync(0xffffffffu, t1, 2));

        const float nm0 = fmaxf(m0, t0);
        const float nm1 = fmaxf(m1, t1);
        const float c0  = ex2f(m0 - nm0);
        const float c1  = ex2f(m1 - nm1);

        float rs0 = 0.f, rs1 = 0.f;
        #pragma unroll
        for (int nd = 0; nd < 8; nd++) {
            sc[nd][0] = ex2f(sc[nd][0] - nm0);
            sc[nd][1] = ex2f(sc[nd][1] - nm0);
            sc[nd][2] = ex2f(sc[nd][2] - nm1);
            sc[nd][3] = ex2f(sc[nd][3] - nm1);
            rs0 += sc[nd][0] + sc[nd][1];
            rs1 += sc[nd][2] + sc[nd][3];
        }
        rs0 += __shfl_xor_sync(0xffffffffu, rs0, 1);
        rs0 += __shfl_xor_sync(0xffffffffu, rs0, 2);
        rs1 += __shfl_xor_sync(0xffffffffu, rs1, 1);
        rs1 += __shfl_xor_sync(0xffffffffu, rs1, 2);

        l0 = l0 * c0 + rs0;
        l1 = l1 * c1 + rs1;
        #pragma unroll
        for (int nd = 0; nd < 4; nd++) {
            o[nd][0] *= c0; o[nd][1] *= c0;
            o[nd][2] *= c1; o[nd][3] *= c1;
        }
        m0 = nm0; m1 = nm1;

        // ---- PV (3xBF16): P repacked directly (no shuffles), V via trans ----
        #pragma unroll
        for (int kb = 0; kb < 4; kb++) {
            unsigned ph[4], pl[4];
            bsplit2(sc[2 * kb][0],     sc[2 * kb][1],     ph[0], pl[0]);
            bsplit2(sc[2 * kb][2],     sc[2 * kb][3],     ph[1], pl[1]);
            bsplit2(sc[2 * kb + 1][0], sc[2 * kb + 1][1], ph[2], pl[2]);
            bsplit2(sc[2 * kb + 1][2], sc[2 * kb + 1][3], ph[3], pl[3]);
            #pragma unroll
            for (int dp = 0; dp < 2; dp++) {
                const int row = kb * 16 + ((lm & 1) << 3) + lr;
                const int u   = dp * 2 + (lm >> 1);
                uint4 vh, vl;
                ldsm4t(vh, vBase + swz(row, u) * 16);
                ldsm4t(vl, vBase + swz(row, u + 4) * 16);
                mma_bf16(o[2 * dp],     ph, vh.x, vh.y);
                mma_bf16(o[2 * dp],     ph, vl.x, vl.y);
                mma_bf16(o[2 * dp],     pl, vh.x, vh.y);
                mma_bf16(o[2 * dp + 1], ph, vh.z, vh.w);
                mma_bf16(o[2 * dp + 1], ph, vl.z, vl.w);
                mma_bf16(o[2 * dp + 1], pl, vh.z, vh.w);
            }
        }
        __syncthreads();
    }

    // ---- epilogue ----
    const float i0 = 1.0f / l0;
    const float i1 = 1.0f / l1;
    const int n = nh >> 4;
    float* op0 = g_O + ((size_t)(q0 + g)     * NB + n) * EMB + h * HD;
    float* op1 = g_O + ((size_t)(q0 + g + 8) * NB + n) * EMB + h * HD;
    #pragma unroll
    for (int nd = 0; nd < 4; nd++) {
        const int col = nd * 8 + 2 * t;
        *(float2*)(op0 + col) = make_float2(o[nd][0] * i0, o[nd][1] * i0);
        *(float2*)(op1 + col) = make_float2(o[nd][2] * i1, o[nd][3] * i1);
    }
}

// ---------------------------------------------------------------------------
extern "C" void kernel_launch(void* const* d_in, const int* in_sizes, int n_in,
                              void* d_out, int out_size)
{
    const float* query   = (const float*)d_in[0];
    const float* key_in  = (const float*)d_in[1];
    const float* value   = (const float*)d_in[2];
    const float* scaling = (const float*)d_in[3];
    const float* in_w    = (const float*)d_in[4];
    const float* in_b    = (const float*)d_in[5];
    const float* pn_w    = (const float*)d_in[6];
    const float* pn_b    = (const float*)d_in[7];
    const float* out_w   = (const float*)d_in[8];
    const float* out_b   = (const float*)d_in[9];
    float* out = (float*)d_out;

    // 1) QKV projections (LayerNorm for K/V fused into the epilogue)
    dim3 gproj(ROWS / 128, EMB / 64, 3);
    gemm_mma_kernel<0><<<gproj, 256>>>(query, key_in, value, in_w, in_b, nullptr,
                                       pn_w, pn_b);

    // 2) Flash attention
    dim3 gattn(LQ / 128, NB * NH);
    attn_mma_kernel<<<gattn, 256>>>(scaling);

    // 3) Output projection -> d_out
    dim3 gout(ROWS / 128, EMB / 64, 1);
    gemm_mma_kernel<1><<<gout, 256>>>(nullptr, nullptr, nullptr, out_w, out_b, out,
                                      nullptr, nullptr);
}

// round 14
// speedup vs baseline: 2.4055x; 1.2327x over previous
#include <cuda_runtime.h>
#include <cuda_bf16.h>

#define LQ  2048
#define SK  2048
#define NB  4
#define EMB 512
#define NH  16
#define HD  32
#define ROWS (LQ * NB)   // 8192

// ---------------------------------------------------------------------------
// Global scratch: everything bf16 hi/lo, pre-swizzled smem images.
//  Q/K/V: [nh(64)][chunk(32)][512 uint4]   (64 rows x 8 units, swz layout)
//  O:     [e-chunk(16)][row-block(64)][1024 uint4] (128 rows x 8 units)
//  W:     [z(4)][n-block(8)][k-chunk(16)][512 uint4]
// ---------------------------------------------------------------------------
__device__ uint4 g_Qb[64 * 32 * 512];
__device__ uint4 g_Kb[64 * 32 * 512];
__device__ uint4 g_Vb[64 * 32 * 512];
__device__ uint4 g_Ob[16 * 64 * 1024];
__device__ uint4 g_Wb[4 * 8 * 16 * 512];

// ---------------------------------------------------------------------------
// helpers
// ---------------------------------------------------------------------------
__device__ __forceinline__ void mma_bf16(float* c, const unsigned* a,
                                         unsigned b0, unsigned b1) {
    asm volatile(
        "mma.sync.aligned.m16n8k16.row.col.f32.bf16.bf16.f32 "
        "{%0,%1,%2,%3}, {%4,%5,%6,%7}, {%8,%9}, {%0,%1,%2,%3};"
        : "+f"(c[0]), "+f"(c[1]), "+f"(c[2]), "+f"(c[3])
        : "r"(a[0]), "r"(a[1]), "r"(a[2]), "r"(a[3]), "r"(b0), "r"(b1));
}
__device__ __forceinline__ void bsplit2(float x, float y, unsigned &hi, unsigned &lo) {
    __nv_bfloat162 h = __floats2bfloat162_rn(x, y);
    const float hx = __bfloat162float(h.x);
    const float hy = __bfloat162float(h.y);
    __nv_bfloat162 l = __floats2bfloat162_rn(x - hx, y - hy);
    hi = *reinterpret_cast<unsigned*>(&h);
    lo = *reinterpret_cast<unsigned*>(&l);
}
__device__ __forceinline__ void pack8(const float4 a, const float4 b,
                                      uint4 &hi, uint4 &lo) {
    bsplit2(a.x, a.y, hi.x, lo.x);
    bsplit2(a.z, a.w, hi.y, lo.y);
    bsplit2(b.x, b.y, hi.z, lo.z);
    bsplit2(b.z, b.w, hi.w, lo.w);
}
__device__ __forceinline__ void ldsm4(uint4 &d, unsigned addr) {
    asm volatile("ldmatrix.sync.aligned.m8n8.x4.shared.b16 {%0,%1,%2,%3}, [%4];"
                 : "=r"(d.x), "=r"(d.y), "=r"(d.z), "=r"(d.w) : "r"(addr));
}
__device__ __forceinline__ void ldsm4t(uint4 &d, unsigned addr) {
    asm volatile("ldmatrix.sync.aligned.m8n8.x4.trans.shared.b16 {%0,%1,%2,%3}, [%4];"
                 : "=r"(d.x), "=r"(d.y), "=r"(d.z), "=r"(d.w) : "r"(addr));
}
__device__ __forceinline__ int swz(int row, int u) {
    return row * 8 + (u ^ (row & 7));
}
__device__ __forceinline__ float ex2f(float x) {
    float y;
    asm("ex2.approx.ftz.f32 %0, %1;" : "=f"(y) : "f"(x));
    return y;
}
__device__ __forceinline__ unsigned smem_u32(const void* p) {
    return (unsigned)__cvta_generic_to_shared(p);
}
__device__ __forceinline__ void cpa16(unsigned dst, const void* src) {
    asm volatile("cp.async.cg.shared.global [%0], [%1], 16;" :: "r"(dst), "l"(src));
}
#define CPA_COMMIT() asm volatile("cp.async.commit_group;" ::: "memory")
#define CPA_WAIT(n)  asm volatile("cp.async.wait_group %0;" :: "n"(n) : "memory")

// ---------------------------------------------------------------------------
// Weight prep: fp32 -> bf16 hi/lo, swizzled tile images. grid (16, 8, 4).
// ---------------------------------------------------------------------------
__global__ __launch_bounds__(256)
void prep_w_kernel(const float* __restrict__ in_w, const float* __restrict__ out_w)
{
    const int c  = blockIdx.x;   // k-chunk
    const int nb = blockIdx.y;   // 64-row block of output features
    const int z  = blockIdx.z;   // 0..2 in_proj, 3 out_proj
    const int tid = threadIdx.x;
    const int row  = tid >> 2;
    const int colB = (tid & 3) * 8;
    const float* Wsrc = (z < 3) ? (in_w + (size_t)z * EMB * EMB) : out_w;
    const float* p = Wsrc + (size_t)(nb * 64 + row) * EMB + c * 32 + colB;
    uint4 hi, lo;
    pack8(*(const float4*)p, *(const float4*)(p + 4), hi, lo);
    uint4* base = g_Wb + (size_t)((z * 8 + nb) * 16 + c) * 512;
    base[swz(row, colB >> 3)]       = hi;
    base[swz(row, (colB >> 3) + 4)] = lo;
}

// ---------------------------------------------------------------------------
// 3xBF16 GEMM. Block 128x64, BK=32, 256 thr (8 warps 4Mx2N), warptile 32x32.
// B always via cp.async from g_Wb. MODE 0: A = fp32 input, convert+STS path;
// epilogue -> Q (beta*log2e folded) / K,V (LayerNorm) as bf16 hi/lo images.
// MODE 1: A via cp.async from g_Ob; epilogue fp32+bias -> d_out.
// ---------------------------------------------------------------------------
template<int MODE>
__global__ __launch_bounds__(256)
void gemm_mma_kernel(const float* __restrict__ Aq, const float* __restrict__ Ak,
                     const float* __restrict__ Av, const float* __restrict__ bfull,
                     float* __restrict__ outp, const float* __restrict__ pnw,
                     const float* __restrict__ pnb, const float* __restrict__ scaling)
{
    __shared__ uint4 ASm[2][1024];   // 32KB
    __shared__ uint4 BSm[2][512];    // 16KB

    const int tid    = threadIdx.x;
    const int warp   = tid >> 5;
    const int lane   = tid & 31;
    const int g      = lane >> 2;
    const int t      = lane & 3;
    const int warp_m = warp >> 1;
    const int warp_n = warp & 1;
    const int r0     = blockIdx.x * 128;
    const int f0     = blockIdx.y * 64;

    const int zW = (MODE == 0) ? blockIdx.z : 3;
    const uint4* Wt = g_Wb + (size_t)(zW * 8 + blockIdx.y) * 16 * 512;
    const float* bias = (MODE == 0) ? bfull + blockIdx.z * EMB : bfull;

    const float* A = nullptr;
    if (MODE == 0)
        A = (blockIdx.z == 0) ? Aq : (blockIdx.z == 1) ? Ak : Av;

    const int rowA = tid >> 1;
    const int colA = (tid & 1) * 16;

    const unsigned aBase = smem_u32(ASm);
    const unsigned bBase = smem_u32(BSm);
    const int lm = lane >> 3;
    const int lr = lane & 7;

    float acc[2][4][4];
    #pragma unroll
    for (int mi = 0; mi < 2; mi++)
        #pragma unroll
        for (int ni = 0; ni < 4; ni++)
            #pragma unroll
            for (int j = 0; j < 4; j++) acc[mi][ni][j] = 0.f;

    // ---- prologue: chunk 0 ----
    float4 aR[4];
    if (MODE == 0) {
        #pragma unroll
        for (int i = 0; i < 4; i++)
            aR[i] = *(const float4*)(A + (size_t)(r0 + rowA) * EMB + colA + i * 4);
    } else {
        const uint4* Asrc = g_Ob + (size_t)blockIdx.x * 1024;
        #pragma unroll
        for (int k = 0; k < 4; k++)
            cpa16(aBase + (tid + k * 256) * 16, Asrc + tid + k * 256);
    }
    cpa16(bBase + tid * 16, Wt + tid);
    cpa16(bBase + (tid + 256) * 16, Wt + tid + 256);
    CPA_COMMIT();

    for (int c = 0; c < 16; c++) {
        const int cur = c & 1, nxt = cur ^ 1;
        if (MODE == 0) {
            uint4 hi, lo;
            const int u = colA >> 3;
            pack8(aR[0], aR[1], hi, lo);
            ASm[cur][swz(rowA, u)]     = hi;
            ASm[cur][swz(rowA, u + 4)] = lo;
            pack8(aR[2], aR[3], hi, lo);
            ASm[cur][swz(rowA, u + 1)] = hi;
            ASm[cur][swz(rowA, u + 5)] = lo;
        }
        if (c + 1 < 16) {
            const uint4* Bsrc = Wt + (size_t)(c + 1) * 512;
            cpa16(bBase + (nxt * 512 + tid) * 16, Bsrc + tid);
            cpa16(bBase + (nxt * 512 + tid + 256) * 16, Bsrc + tid + 256);
            if (MODE == 1) {
                const uint4* Asrc = g_Ob + (size_t)((c + 1) * 64 + blockIdx.x) * 1024;
                #pragma unroll
                for (int k = 0; k < 4; k++)
                    cpa16(aBase + (nxt * 1024 + tid + k * 256) * 16, Asrc + tid + k * 256);
            }
            CPA_COMMIT();
            if (MODE == 0) {
                #pragma unroll
                for (int i = 0; i < 4; i++)
                    aR[i] = *(const float4*)(A + (size_t)(r0 + rowA) * EMB
                                             + (c + 1) * 32 + colA + i * 4);
            }
            CPA_WAIT(1);
        } else {
            CPA_WAIT(0);
        }
        __syncthreads();

        const unsigned aOff = aBase + cur * (1024 * 16);
        const unsigned bOff = bBase + cur * (512 * 16);
        #pragma unroll
        for (int ks = 0; ks < 2; ks++) {
            uint4 ah[2], al[2], bh[2], bl[2];
            #pragma unroll
            for (int mi = 0; mi < 2; mi++) {
                const int row = warp_m * 32 + mi * 16 + ((lm & 1) << 3) + lr;
                const int u   = ks * 2 + (lm >> 1);
                ldsm4(ah[mi], aOff + swz(row, u) * 16);
                ldsm4(al[mi], aOff + swz(row, u + 4) * 16);
            }
            #pragma unroll
            for (int bi = 0; bi < 2; bi++) {
                const int row = warp_n * 32 + bi * 16 + ((lm >> 1) << 3) + lr;
                const int u   = ks * 2 + (lm & 1);
                ldsm4(bh[bi], bOff + swz(row, u) * 16);
                ldsm4(bl[bi], bOff + swz(row, u + 4) * 16);
            }
            #pragma unroll
            for (int ni = 0; ni < 4; ni++) {
                const int bi = ni >> 1;
                const unsigned h0 = (ni & 1) ? bh[bi].z : bh[bi].x;
                const unsigned h1 = (ni & 1) ? bh[bi].w : bh[bi].y;
                const unsigned l0 = (ni & 1) ? bl[bi].z : bl[bi].x;
                const unsigned l1 = (ni & 1) ? bl[bi].w : bl[bi].y;
                #pragma unroll
                for (int mi = 0; mi < 2; mi++) {
                    mma_bf16(acc[mi][ni], &ah[mi].x, h0, h1);
                    mma_bf16(acc[mi][ni], &ah[mi].x, l0, l1);
                    mma_bf16(acc[mi][ni], &al[mi].x, h0, h1);
                }
            }
        }
        __syncthreads();
    }

    // ---- epilogue ----
    if (MODE == 0) {
        const int z = blockIdx.z;
        const int h = (f0 + warp_n * 32) >> 5;
        unsigned* dw = (unsigned*)((z == 0) ? g_Qb : (z == 1) ? g_Kb : g_Vb);
        const bool doLN = (z != 0);
        const float qscale = doLN ? 1.0f : scaling[h] * 1.4426950408889634f;
        float pwv[8], pbv[8];
        if (doLN) {
            #pragma unroll
            for (int ni = 0; ni < 4; ni++) {
                const int d = ni * 8 + 2 * t;
                pwv[ni * 2]     = pnw[d];
                pwv[ni * 2 + 1] = pnw[d + 1];
                pbv[ni * 2]     = pnb[d];
                pbv[ni * 2 + 1] = pnb[d + 1];
            }
        }
        #pragma unroll
        for (int mi = 0; mi < 2; mi++) {
            float vals[2][8];
            #pragma unroll
            for (int ni = 0; ni < 4; ni++) {
                const int f = f0 + warp_n * 32 + ni * 8 + 2 * t;
                const float b0 = bias[f];
                const float b1 = bias[f + 1];
                vals[0][ni * 2]     = acc[mi][ni][0] + b0;
                vals[0][ni * 2 + 1] = acc[mi][ni][1] + b1;
                vals[1][ni * 2]     = acc[mi][ni][2] + b0;
                vals[1][ni * 2 + 1] = acc[mi][ni][3] + b1;
            }
            #pragma unroll
            for (int rh = 0; rh < 2; rh++) {
                if (doLN) {
                    float s = 0.f, s2 = 0.f;
                    #pragma unroll
                    for (int j = 0; j < 8; j++) {
                        s  += vals[rh][j];
                        s2 += vals[rh][j] * vals[rh][j];
                    }
                    s  += __shfl_xor_sync(0xffffffffu, s, 1);
                    s  += __shfl_xor_sync(0xffffffffu, s, 2);
                    s2 += __shfl_xor_sync(0xffffffffu, s2, 1);
                    s2 += __shfl_xor_sync(0xffffffffu, s2, 2);
                    const float mu  = s * (1.0f / HD);
                    const float var = s2 * (1.0f / HD) - mu * mu;
                    const float inv = rsqrtf(var + 1e-5f);
                    #pragma unroll
                    for (int j = 0; j < 8; j++)
                        vals[rh][j] = (vals[rh][j] - mu) * inv * pwv[j] + pbv[j];
                } else {
                    #pragma unroll
                    for (int j = 0; j < 8; j++) vals[rh][j] *= qscale;
                }
                const int r = r0 + warp_m * 32 + mi * 16 + g + rh * 8;
                const int l = r >> 2, n = r & 3;
                const unsigned base = ((unsigned)(n * NH + h) * 32 + (l >> 6)) * 512;
                const int rowc = l & 63;
                #pragma unroll
                for (int ni = 0; ni < 4; ni++) {
                    unsigned hi, lo;
                    bsplit2(vals[rh][ni * 2], vals[rh][ni * 2 + 1], hi, lo);
                    dw[(base + swz(rowc, ni)) * 4 + t]     = hi;
                    dw[(base + swz(rowc, ni + 4)) * 4 + t] = lo;
                }
            }
        }
    } else {
        #pragma unroll
        for (int mi = 0; mi < 2; mi++) {
            const int rA = r0 + warp_m * 32 + mi * 16 + g;
            const int rB = rA + 8;
            #pragma unroll
            for (int ni = 0; ni < 4; ni++) {
                const float* c = acc[mi][ni];
                const int f  = f0 + warp_n * 32 + ni * 8 + 2 * t;
                const float b0 = bias[f];
                const float b1 = bias[f + 1];
                *(float2*)(outp + (size_t)rA * EMB + f) = make_float2(c[0] + b0, c[1] + b1);
                *(float2*)(outp + (size_t)rB * EMB + f) = make_float2(c[2] + b0, c[3] + b1);
            }
        }
    }
}

// ---------------------------------------------------------------------------
// Flash attention: all operands pre-split bf16 hi/lo in global; per-chunk
// loader = 4 cp.async/thread into a ring-3 smem buffer (1 sync per chunk).
// Q fragments read directly from g_Qb (beta*log2e pre-folded).
// QK and PV = hi*hi + hi*lo + lo*hi. Softmax via ex2.approx.
// Block 256 thr (8 warps), 16 q rows/warp, S-chunks of 64, grid (16, 64).
// ---------------------------------------------------------------------------
__global__ __launch_bounds__(256)
void attn_mma_kernel()
{
    __shared__ uint4 KV[3][1024];   // [stage][K 0..511 | V 512..1023], 48KB

    const int tid  = threadIdx.x;
    const int warp = tid >> 5;
    const int lane = tid & 31;
    const int g    = lane >> 2;
    const int t    = lane & 3;
    const int nh   = blockIdx.y;
    const int h    = nh & (NH - 1);
    const int q0   = blockIdx.x * 128 + warp * 16;

    const unsigned kvB = smem_u32(KV);
    const int lm = lane >> 3;
    const int lr = lane & 7;

    // Q fragments straight from the split image
    const unsigned* Qw = (const unsigned*)g_Qb;
    const unsigned qbase = ((unsigned)nh * 32 + (q0 >> 6)) * 512;
    const int rc = q0 & 63;
    unsigned aqh[2][4], aql[2][4];
    #pragma unroll
    for (int ks = 0; ks < 2; ks++) {
        aqh[ks][0] = Qw[(qbase + swz(rc + g,     2 * ks)) * 4 + t];
        aqh[ks][1] = Qw[(qbase + swz(rc + g + 8, 2 * ks)) * 4 + t];
        aqh[ks][2] = Qw[(qbase + swz(rc + g,     2 * ks + 1)) * 4 + t];
        aqh[ks][3] = Qw[(qbase + swz(rc + g + 8, 2 * ks + 1)) * 4 + t];
        aql[ks][0] = Qw[(qbase + swz(rc + g,     2 * ks + 4)) * 4 + t];
        aql[ks][1] = Qw[(qbase + swz(rc + g + 8, 2 * ks + 4)) * 4 + t];
        aql[ks][2] = Qw[(qbase + swz(rc + g,     2 * ks + 5)) * 4 + t];
        aql[ks][3] = Qw[(qbase + swz(rc + g + 8, 2 * ks + 5)) * 4 + t];
    }

    float m0 = -1e30f, m1 = -1e30f, l0 = 0.f, l1 = 0.f;
    float o[4][4];
    #pragma unroll
    for (int nd = 0; nd < 4; nd++)
        #pragma unroll
        for (int j = 0; j < 4; j++) o[nd][j] = 0.f;

    const uint4* Ksrc = g_Kb + (size_t)nh * 32 * 512;
    const uint4* Vsrc = g_Vb + (size_t)nh * 32 * 512;

    // prologue: chunk 0 -> stage 0
    cpa16(kvB + tid * 16,               Ksrc + tid);
    cpa16(kvB + (tid + 256) * 16,       Ksrc + tid + 256);
    cpa16(kvB + (512 + tid) * 16,       Vsrc + tid);
    cpa16(kvB + (512 + tid + 256) * 16, Vsrc + tid + 256);
    CPA_COMMIT();

    int st = 0;
    for (int c = 0; c < 32; c++) {
        if (c + 1 < 32) {
            const int ns = (st + 1 == 3) ? 0 : st + 1;
            const unsigned dB = kvB + ns * 16384;
            const uint4* Kc = Ksrc + (size_t)(c + 1) * 512;
            const uint4* Vc = Vsrc + (size_t)(c + 1) * 512;
            cpa16(dB + tid * 16,               Kc + tid);
            cpa16(dB + (tid + 256) * 16,       Kc + tid + 256);
            cpa16(dB + (512 + tid) * 16,       Vc + tid);
            cpa16(dB + (512 + tid + 256) * 16, Vc + tid + 256);
            CPA_COMMIT();
            CPA_WAIT(1);
        } else {
            CPA_WAIT(0);
        }
        __syncthreads();

        const unsigned ksb = kvB + st * 16384;
        const unsigned vsb = ksb + 8192;

        // ---- QK scores (3xBF16): 8 s-tiles of 16x8 ----
        float sc[8][4];
        #pragma unroll
        for (int nd = 0; nd < 8; nd++) {
            sc[nd][0] = sc[nd][1] = sc[nd][2] = sc[nd][3] = 0.f;
            const int row = nd * 8 + lr;
            uint4 kh, kl;
            ldsm4(kh, ksb + swz(row, lm) * 16);
            ldsm4(kl, ksb + swz(row, lm + 4) * 16);
            mma_bf16(sc[nd], aqh[0], kh.x, kh.y);
            mma_bf16(sc[nd], aqh[1], kh.z, kh.w);
            mma_bf16(sc[nd], aqh[0], kl.x, kl.y);
            mma_bf16(sc[nd], aqh[1], kl.z, kl.w);
            mma_bf16(sc[nd], aql[0], kh.x, kh.y);
            mma_bf16(sc[nd], aql[1], kh.z, kh.w);
        }

        // ---- online softmax (exp2 domain) ----
        float t0 = -1e30f, t1 = -1e30f;
        #pragma unroll
        for (int nd = 0; nd < 8; nd++) {
            t0 = fmaxf(t0, fmaxf(sc[nd][0], sc[nd][1]));
            t1 = fmaxf(t1, fmaxf(sc[nd][2], sc[nd][3]));
        }
        t0 = fmaxf(t0, __shfl_xor_sync(0xffffffffu, t0, 1));
        t0 = fmaxf(t0, __shfl_xor_sync(0xffffffffu, t0, 2));
        t1 = fmaxf(t1, __shfl_xor_sync(0xffffffffu, t1, 1));
        t1 = fmaxf(t1, __shfl_xor_sync(0xffffffffu, t1, 2));

        const float nm0 = fmaxf(m0, t0);
        const float nm1 = fmaxf(m1, t1);
        const float c0  = ex2f(m0 - nm0);
        const float c1  = ex2f(m1 - nm1);

        float rs0 = 0.f, rs1 = 0.f;
        #pragma unroll
        for (int nd = 0; nd < 8; nd++) {
            sc[nd][0] = ex2f(sc[nd][0] - nm0);
            sc[nd][1] = ex2f(sc[nd][1] - nm0);
            sc[nd][2] = ex2f(sc[nd][2] - nm1);
            sc[nd][3] = ex2f(sc[nd][3] - nm1);
            rs0 += sc[nd][0] + sc[nd][1];
            rs1 += sc[nd][2] + sc[nd][3];
        }
        rs0 += __shfl_xor_sync(0xffffffffu, rs0, 1);
        rs0 += __shfl_xor_sync(0xffffffffu, rs0, 2);
        rs1 += __shfl_xor_sync(0xffffffffu, rs1, 1);
        rs1 += __shfl_xor_sync(0xffffffffu, rs1, 2);

        l0 = l0 * c0 + rs0;
        l1 = l1 * c1 + rs1;
        #pragma unroll
        for (int nd = 0; nd < 4; nd++) {
            o[nd][0] *= c0; o[nd][1] *= c0;
            o[nd][2] *= c1; o[nd][3] *= c1;
        }
        m0 = nm0; m1 = nm1;

        // ---- PV (3xBF16): P repacked directly, V via ldmatrix.trans ----
        #pragma unroll
        for (int kb = 0; kb < 4; kb++) {
            unsigned ph[4], pl[4];
            bsplit2(sc[2 * kb][0],     sc[2 * kb][1],     ph[0], pl[0]);
            bsplit2(sc[2 * kb][2],     sc[2 * kb][3],     ph[1], pl[1]);
            bsplit2(sc[2 * kb + 1][0], sc[2 * kb + 1][1], ph[2], pl[2]);
            bsplit2(sc[2 * kb + 1][2], sc[2 * kb + 1][3], ph[3], pl[3]);
            #pragma unroll
            for (int dp = 0; dp < 2; dp++) {
                const int row = kb * 16 + ((lm & 1) << 3) + lr;
                const int u   = dp * 2 + (lm >> 1);
                uint4 vh, vl;
                ldsm4t(vh, vsb + swz(row, u) * 16);
                ldsm4t(vl, vsb + swz(row, u + 4) * 16);
                mma_bf16(o[2 * dp],     ph, vh.x, vh.y);
                mma_bf16(o[2 * dp],     ph, vl.x, vl.y);
                mma_bf16(o[2 * dp],     pl, vh.x, vh.y);
                mma_bf16(o[2 * dp + 1], ph, vh.z, vh.w);
                mma_bf16(o[2 * dp + 1], ph, vl.z, vl.w);
                mma_bf16(o[2 * dp + 1], pl, vh.z, vh.w);
            }
        }

        st = (st + 1 == 3) ? 0 : st + 1;
    }

    // ---- epilogue: write O in gemm<1>'s A-tile image (bf16 hi/lo) ----
    const float i0 = 1.0f / l0;
    const float i1 = 1.0f / l1;
    const int n = nh >> 4;
    unsigned* Ow = (unsigned*)g_Ob;
    #pragma unroll
    for (int rh = 0; rh < 2; rh++) {
        const int r = (q0 + g + rh * 8) * NB + n;
        const unsigned base = (unsigned)(h * 64 + (r >> 7)) * 1024;
        const int rowc = r & 127;
        const float inv = rh ? i1 : i0;
        #pragma unroll
        for (int nd = 0; nd < 4; nd++) {
            unsigned hi, lo;
            bsplit2(o[nd][rh * 2] * inv, o[nd][rh * 2 + 1] * inv, hi, lo);
            Ow[(base + swz(rowc, nd)) * 4 + t]     = hi;
            Ow[(base + swz(rowc, nd + 4)) * 4 + t] = lo;
        }
    }
}

// ---------------------------------------------------------------------------
extern "C" void kernel_launch(void* const* d_in, const int* in_sizes, int n_in,
                              void* d_out, int out_size)
{
    const float* query   = (const float*)d_in[0];
    const float* key_in  = (const float*)d_in[1];
    const float* value   = (const float*)d_in[2];
    const float* scaling = (const float*)d_in[3];
    const float* in_w    = (const float*)d_in[4];
    const float* in_b    = (const float*)d_in[5];
    const float* pn_w    = (const float*)d_in[6];
    const float* pn_b    = (const float*)d_in[7];
    const float* out_w   = (const float*)d_in[8];
    const float* out_b   = (const float*)d_in[9];
    float* out = (float*)d_out;

    // 0) weights -> bf16 hi/lo swizzled images
    prep_w_kernel<<<dim3(16, 8, 4), 256>>>(in_w, out_w);

    // 1) QKV projections (+LN for K/V, +beta*log2e for Q) -> split images
    gemm_mma_kernel<0><<<dim3(ROWS / 128, EMB / 64, 3), 256>>>(
        query, key_in, value, in_b, nullptr, pn_w, pn_b, scaling);

    // 2) Flash attention -> O split image
    attn_mma_kernel<<<dim3(LQ / 128, NB * NH), 256>>>();

    // 3) Output projection -> d_out
    gemm_mma_kernel<1><<<dim3(ROWS / 128, EMB / 64, 1), 256>>>(
        nullptr, nullptr, nullptr, out_b, out, nullptr, nullptr, nullptr);
}

// round 15
// speedup vs baseline: 2.5984x; 1.0802x over previous
#include <cuda_runtime.h>
#include <cuda_bf16.h>

#define LQ  2048
#define SK  2048
#define NB  4
#define EMB 512
#define NH  16
#define HD  32
#define ROWS (LQ * NB)   // 8192

// ---------------------------------------------------------------------------
// Global scratch: everything bf16 hi/lo, pre-swizzled smem images.
//  Q/K/V: [nh(64)][chunk(32)][512 uint4]   (64 rows x 8 units, swz layout)
//  O:     [e-chunk(16)][row-block(64)][1024 uint4] (128 rows x 8 units)
//  W:     [z(4)][n-block(8)][k-chunk(16)][512 uint4]
//  I:     [z(3)][k-chunk(16)][row-block(64)][1024 uint4]  (converted inputs)
// ---------------------------------------------------------------------------
__device__ uint4 g_Qb[64 * 32 * 512];
__device__ uint4 g_Kb[64 * 32 * 512];
__device__ uint4 g_Vb[64 * 32 * 512];
__device__ uint4 g_Ob[16 * 64 * 1024];
__device__ uint4 g_Wb[4 * 8 * 16 * 512];
__device__ uint4 g_Ib[3 * 16 * 64 * 1024];

// ---------------------------------------------------------------------------
// helpers
// ---------------------------------------------------------------------------
__device__ __forceinline__ void mma_bf16(float* c, const unsigned* a,
                                         unsigned b0, unsigned b1) {
    asm volatile(
        "mma.sync.aligned.m16n8k16.row.col.f32.bf16.bf16.f32 "
        "{%0,%1,%2,%3}, {%4,%5,%6,%7}, {%8,%9}, {%0,%1,%2,%3};"
        : "+f"(c[0]), "+f"(c[1]), "+f"(c[2]), "+f"(c[3])
        : "r"(a[0]), "r"(a[1]), "r"(a[2]), "r"(a[3]), "r"(b0), "r"(b1));
}
__device__ __forceinline__ void bsplit2(float x, float y, unsigned &hi, unsigned &lo) {
    __nv_bfloat162 h = __floats2bfloat162_rn(x, y);
    const float hx = __bfloat162float(h.x);
    const float hy = __bfloat162float(h.y);
    __nv_bfloat162 l = __floats2bfloat162_rn(x - hx, y - hy);
    hi = *reinterpret_cast<unsigned*>(&h);
    lo = *reinterpret_cast<unsigned*>(&l);
}
__device__ __forceinline__ void pack8(const float4 a, const float4 b,
                                      uint4 &hi, uint4 &lo) {
    bsplit2(a.x, a.y, hi.x, lo.x);
    bsplit2(a.z, a.w, hi.y, lo.y);
    bsplit2(b.x, b.y, hi.z, lo.z);
    bsplit2(b.z, b.w, hi.w, lo.w);
}
__device__ __forceinline__ void ldsm4(uint4 &d, unsigned addr) {
    asm volatile("ldmatrix.sync.aligned.m8n8.x4.shared.b16 {%0,%1,%2,%3}, [%4];"
                 : "=r"(d.x), "=r"(d.y), "=r"(d.z), "=r"(d.w) : "r"(addr));
}
__device__ __forceinline__ void ldsm4t(uint4 &d, unsigned addr) {
    asm volatile("ldmatrix.sync.aligned.m8n8.x4.trans.shared.b16 {%0,%1,%2,%3}, [%4];"
                 : "=r"(d.x), "=r"(d.y), "=r"(d.z), "=r"(d.w) : "r"(addr));
}
__device__ __forceinline__ int swz(int row, int u) {
    return row * 8 + (u ^ (row & 7));
}
__device__ __forceinline__ float ex2f(float x) {
    float y;
    asm("ex2.approx.ftz.f32 %0, %1;" : "=f"(y) : "f"(x));
    return y;
}
__device__ __forceinline__ unsigned smem_u32(const void* p) {
    return (unsigned)__cvta_generic_to_shared(p);
}
__device__ __forceinline__ void cpa16(unsigned dst, const void* src) {
    asm volatile("cp.async.cg.shared.global [%0], [%1], 16;" :: "r"(dst), "l"(src));
}
#define CPA_COMMIT() asm volatile("cp.async.commit_group;" ::: "memory")
#define CPA_WAIT(n)  asm volatile("cp.async.wait_group %0;" :: "n"(n) : "memory")

// ---------------------------------------------------------------------------
// Weight prep: fp32 -> bf16 hi/lo, swizzled tile images. grid (16, 8, 4).
// ---------------------------------------------------------------------------
__global__ __launch_bounds__(256)
void prep_w_kernel(const float* __restrict__ in_w, const float* __restrict__ out_w)
{
    const int c  = blockIdx.x;
    const int nb = blockIdx.y;
    const int z  = blockIdx.z;
    const int tid = threadIdx.x;
    const int row  = tid >> 2;
    const int colB = (tid & 3) * 8;
    const float* Wsrc = (z < 3) ? (in_w + (size_t)z * EMB * EMB) : out_w;
    const float* p = Wsrc + (size_t)(nb * 64 + row) * EMB + c * 32 + colB;
    uint4 hi, lo;
    pack8(*(const float4*)p, *(const float4*)(p + 4), hi, lo);
    uint4* base = g_Wb + (size_t)((z * 8 + nb) * 16 + c) * 512;
    base[swz(row, colB >> 3)]       = hi;
    base[swz(row, (colB >> 3) + 4)] = lo;
}

// ---------------------------------------------------------------------------
// Input prep: query/key_in/value fp32 -> bf16 hi/lo A-tile images.
// grid (16 k-chunks, 64 row-blocks, 3), 256 thr.
// ---------------------------------------------------------------------------
__global__ __launch_bounds__(256)
void prep_x_kernel(const float* __restrict__ q, const float* __restrict__ k,
                   const float* __restrict__ v)
{
    const int c  = blockIdx.x;
    const int rb = blockIdx.y;
    const int z  = blockIdx.z;
    const int tid = threadIdx.x;
    const int row  = tid >> 1;
    const int colA = (tid & 1) * 16;
    const float* X = (z == 0) ? q : (z == 1) ? k : v;
    const float* p = X + (size_t)(rb * 128 + row) * EMB + c * 32 + colA;
    uint4* img = g_Ib + (size_t)((z * 16 + c) * 64 + rb) * 1024;
    const int u = colA >> 3;
    uint4 hi, lo;
    pack8(*(const float4*)p, *(const float4*)(p + 4), hi, lo);
    img[swz(row, u)]     = hi;
    img[swz(row, u + 4)] = lo;
    pack8(*(const float4*)(p + 8), *(const float4*)(p + 12), hi, lo);
    img[swz(row, u + 1)] = hi;
    img[swz(row, u + 5)] = lo;
}

// ---------------------------------------------------------------------------
// 3xBF16 GEMM. Block 128x64, BK=32, 256 thr (8 warps 4Mx2N), warptile 32x32.
// A and B both stream via cp.async from pre-split images (g_Ib/g_Ob, g_Wb).
// One sync per chunk: [wait(0); sync; cpa(next); commit; compute].
// MODE 0 epilogue: Q (beta*log2e folded) / K,V (LayerNorm) -> split images.
// MODE 1 epilogue: fp32 + bias -> d_out.
// ---------------------------------------------------------------------------
template<int MODE>
__global__ __launch_bounds__(256)
void gemm_mma_kernel(const float* __restrict__ bfull, float* __restrict__ outp,
                     const float* __restrict__ pnw, const float* __restrict__ pnb,
                     const float* __restrict__ scaling)
{
    __shared__ uint4 ASm[2][1024];   // 32KB
    __shared__ uint4 BSm[2][512];    // 16KB

    const int tid    = threadIdx.x;
    const int warp   = tid >> 5;
    const int lane   = tid & 31;
    const int g      = lane >> 2;
    const int t      = lane & 3;
    const int warp_m = warp >> 1;
    const int warp_n = warp & 1;
    const int r0     = blockIdx.x * 128;
    const int f0     = blockIdx.y * 64;

    const int zW = (MODE == 0) ? blockIdx.z : 3;
    const uint4* Wt   = g_Wb + (size_t)(zW * 8 + blockIdx.y) * 16 * 512;
    const uint4* Aimg = (MODE == 0) ? (g_Ib + (size_t)blockIdx.z * 16 * 64 * 1024)
                                    : g_Ob;
    const float* bias = (MODE == 0) ? bfull + blockIdx.z * EMB : bfull;

    const unsigned aBase = smem_u32(ASm);
    const unsigned bBase = smem_u32(BSm);
    const int lm = lane >> 3;
    const int lr = lane & 7;

    float acc[2][4][4];
    #pragma unroll
    for (int mi = 0; mi < 2; mi++)
        #pragma unroll
        for (int ni = 0; ni < 4; ni++)
            #pragma unroll
            for (int j = 0; j < 4; j++) acc[mi][ni][j] = 0.f;

    // ---- prologue: chunk 0 ----
    {
        const uint4* Asrc = Aimg + (size_t)blockIdx.x * 1024;
        #pragma unroll
        for (int k = 0; k < 4; k++)
            cpa16(aBase + (tid + k * 256) * 16, Asrc + tid + k * 256);
        cpa16(bBase + tid * 16, Wt + tid);
        cpa16(bBase + (tid + 256) * 16, Wt + tid + 256);
        CPA_COMMIT();
    }

    for (int c = 0; c < 16; c++) {
        const int cur = c & 1, nxt = cur ^ 1;
        CPA_WAIT(0);
        __syncthreads();
        if (c + 1 < 16) {
            const uint4* Asrc = Aimg + (size_t)((c + 1) * 64 + blockIdx.x) * 1024;
            #pragma unroll
            for (int k = 0; k < 4; k++)
                cpa16(aBase + (nxt * 1024 + tid + k * 256) * 16, Asrc + tid + k * 256);
            const uint4* Bsrc = Wt + (size_t)(c + 1) * 512;
            cpa16(bBase + (nxt * 512 + tid) * 16, Bsrc + tid);
            cpa16(bBase + (nxt * 512 + tid + 256) * 16, Bsrc + tid + 256);
            CPA_COMMIT();
        }

        const unsigned aOff = aBase + cur * (1024 * 16);
        const unsigned bOff = bBase + cur * (512 * 16);
        #pragma unroll
        for (int ks = 0; ks < 2; ks++) {
            uint4 ah[2], al[2], bh[2], bl[2];
            #pragma unroll
            for (int mi = 0; mi < 2; mi++) {
                const int row = warp_m * 32 + mi * 16 + ((lm & 1) << 3) + lr;
                const int u   = ks * 2 + (lm >> 1);
                ldsm4(ah[mi], aOff + swz(row, u) * 16);
                ldsm4(al[mi], aOff + swz(row, u + 4) * 16);
            }
            #pragma unroll
            for (int bi = 0; bi < 2; bi++) {
                const int row = warp_n * 32 + bi * 16 + ((lm >> 1) << 3) + lr;
                const int u   = ks * 2 + (lm & 1);
                ldsm4(bh[bi], bOff + swz(row, u) * 16);
                ldsm4(bl[bi], bOff + swz(row, u + 4) * 16);
            }
            #pragma unroll
            for (int ni = 0; ni < 4; ni++) {
                const int bi = ni >> 1;
                const unsigned h0 = (ni & 1) ? bh[bi].z : bh[bi].x;
                const unsigned h1 = (ni & 1) ? bh[bi].w : bh[bi].y;
                const unsigned l0 = (ni & 1) ? bl[bi].z : bl[bi].x;
                const unsigned l1 = (ni & 1) ? bl[bi].w : bl[bi].y;
                #pragma unroll
                for (int mi = 0; mi < 2; mi++) {
                    mma_bf16(acc[mi][ni], &ah[mi].x, h0, h1);
                    mma_bf16(acc[mi][ni], &ah[mi].x, l0, l1);
                    mma_bf16(acc[mi][ni], &al[mi].x, h0, h1);
                }
            }
        }
    }

    // ---- epilogue ----
    if (MODE == 0) {
        const int z = blockIdx.z;
        const int h = (f0 + warp_n * 32) >> 5;
        unsigned* dw = (unsigned*)((z == 0) ? g_Qb : (z == 1) ? g_Kb : g_Vb);
        const bool doLN = (z != 0);
        const float qscale = doLN ? 1.0f : scaling[h] * 1.4426950408889634f;
        float pwv[8], pbv[8];
        if (doLN) {
            #pragma unroll
            for (int ni = 0; ni < 4; ni++) {
                const int d = ni * 8 + 2 * t;
                pwv[ni * 2]     = pnw[d];
                pwv[ni * 2 + 1] = pnw[d + 1];
                pbv[ni * 2]     = pnb[d];
                pbv[ni * 2 + 1] = pnb[d + 1];
            }
        }
        #pragma unroll
        for (int mi = 0; mi < 2; mi++) {
            float vals[2][8];
            #pragma unroll
            for (int ni = 0; ni < 4; ni++) {
                const int f = f0 + warp_n * 32 + ni * 8 + 2 * t;
                const float b0 = bias[f];
                const float b1 = bias[f + 1];
                vals[0][ni * 2]     = acc[mi][ni][0] + b0;
                vals[0][ni * 2 + 1] = acc[mi][ni][1] + b1;
                vals[1][ni * 2]     = acc[mi][ni][2] + b0;
                vals[1][ni * 2 + 1] = acc[mi][ni][3] + b1;
            }
            #pragma unroll
            for (int rh = 0; rh < 2; rh++) {
                if (doLN) {
                    float s = 0.f, s2 = 0.f;
                    #pragma unroll
                    for (int j = 0; j < 8; j++) {
                        s  += vals[rh][j];
                        s2 += vals[rh][j] * vals[rh][j];
                    }
                    s  += __shfl_xor_sync(0xffffffffu, s, 1);
                    s  += __shfl_xor_sync(0xffffffffu, s, 2);
                    s2 += __shfl_xor_sync(0xffffffffu, s2, 1);
                    s2 += __shfl_xor_sync(0xffffffffu, s2, 2);
                    const float mu  = s * (1.0f / HD);
                    const float var = s2 * (1.0f / HD) - mu * mu;
                    const float inv = rsqrtf(var + 1e-5f);
                    #pragma unroll
                    for (int j = 0; j < 8; j++)
                        vals[rh][j] = (vals[rh][j] - mu) * inv * pwv[j] + pbv[j];
                } else {
                    #pragma unroll
                    for (int j = 0; j < 8; j++) vals[rh][j] *= qscale;
                }
                const int r = r0 + warp_m * 32 + mi * 16 + g + rh * 8;
                const int l = r >> 2, n = r & 3;
                const unsigned base = ((unsigned)(n * NH + h) * 32 + (l >> 6)) * 512;
                const int rowc = l & 63;
                #pragma unroll
                for (int ni = 0; ni < 4; ni++) {
                    unsigned hi, lo;
                    bsplit2(vals[rh][ni * 2], vals[rh][ni * 2 + 1], hi, lo);
                    dw[(base + swz(rowc, ni)) * 4 + t]     = hi;
                    dw[(base + swz(rowc, ni + 4)) * 4 + t] = lo;
                }
            }
        }
    } else {
        #pragma unroll
        for (int mi = 0; mi < 2; mi++) {
            const int rA = r0 + warp_m * 32 + mi * 16 + g;
            const int rB = rA + 8;
            #pragma unroll
            for (int ni = 0; ni < 4; ni++) {
                const float* c = acc[mi][ni];
                const int f  = f0 + warp_n * 32 + ni * 8 + 2 * t;
                const float b0 = bias[f];
                const float b1 = bias[f + 1];
                *(float2*)(outp + (size_t)rA * EMB + f) = make_float2(c[0] + b0, c[1] + b1);
                *(float2*)(outp + (size_t)rB * EMB + f) = make_float2(c[2] + b0, c[3] + b1);
            }
        }
    }
}

// ---------------------------------------------------------------------------
// Flash attention (unchanged from R14): pre-split bf16 hi/lo operands,
// ring-3 cp.async K/V, QK and PV = hi*hi + hi*lo + lo*hi, ex2 softmax.
// Block 256 thr (8 warps), 16 q rows/warp, S-chunks of 64, grid (16, 64).
// ---------------------------------------------------------------------------
__global__ __launch_bounds__(256)
void attn_mma_kernel()
{
    __shared__ uint4 KV[3][1024];   // [stage][K 0..511 | V 512..1023], 48KB

    const int tid  = threadIdx.x;
    const int warp = tid >> 5;
    const int lane = tid & 31;
    const int g    = lane >> 2;
    const int t    = lane & 3;
    const int nh   = blockIdx.y;
    const int h    = nh & (NH - 1);
    const int q0   = blockIdx.x * 128 + warp * 16;

    const unsigned kvB = smem_u32(KV);
    const int lm = lane >> 3;
    const int lr = lane & 7;

    // Q fragments straight from the split image
    const unsigned* Qw = (const unsigned*)g_Qb;
    const unsigned qbase = ((unsigned)nh * 32 + (q0 >> 6)) * 512;
    const int rc = q0 & 63;
    unsigned aqh[2][4], aql[2][4];
    #pragma unroll
    for (int ks = 0; ks < 2; ks++) {
        aqh[ks][0] = Qw[(qbase + swz(rc + g,     2 * ks)) * 4 + t];
        aqh[ks][1] = Qw[(qbase + swz(rc + g + 8, 2 * ks)) * 4 + t];
        aqh[ks][2] = Qw[(qbase + swz(rc + g,     2 * ks + 1)) * 4 + t];
        aqh[ks][3] = Qw[(qbase + swz(rc + g + 8, 2 * ks + 1)) * 4 + t];
        aql[ks][0] = Qw[(qbase + swz(rc + g,     2 * ks + 4)) * 4 + t];
        aql[ks][1] = Qw[(qbase + swz(rc + g + 8, 2 * ks + 4)) * 4 + t];
        aql[ks][2] = Qw[(qbase + swz(rc + g,     2 * ks + 5)) * 4 + t];
        aql[ks][3] = Qw[(qbase + swz(rc + g + 8, 2 * ks + 5)) * 4 + t];
    }

    float m0 = -1e30f, m1 = -1e30f, l0 = 0.f, l1 = 0.f;
    float o[4][4];
    #pragma unroll
    for (int nd = 0; nd < 4; nd++)
        #pragma unroll
        for (int j = 0; j < 4; j++) o[nd][j] = 0.f;

    const uint4* Ksrc = g_Kb + (size_t)nh * 32 * 512;
    const uint4* Vsrc = g_Vb + (size_t)nh * 32 * 512;

    cpa16(kvB + tid * 16,               Ksrc + tid);
    cpa16(kvB + (tid + 256) * 16,       Ksrc + tid + 256);
    cpa16(kvB + (512 + tid) * 16,       Vsrc + tid);
    cpa16(kvB + (512 + tid + 256) * 16, Vsrc + tid + 256);
    CPA_COMMIT();

    int st = 0;
    for (int c = 0; c < 32; c++) {
        if (c + 1 < 32) {
            const int ns = (st + 1 == 3) ? 0 : st + 1;
            const unsigned dB = kvB + ns * 16384;
            const uint4* Kc = Ksrc + (size_t)(c + 1) * 512;
            const uint4* Vc = Vsrc + (size_t)(c + 1) * 512;
            cpa16(dB + tid * 16,               Kc + tid);
            cpa16(dB + (tid + 256) * 16,       Kc + tid + 256);
            cpa16(dB + (512 + tid) * 16,       Vc + tid);
            cpa16(dB + (512 + tid + 256) * 16, Vc + tid + 256);
            CPA_COMMIT();
            CPA_WAIT(1);
        } else {
            CPA_WAIT(0);
        }
        __syncthreads();

        const unsigned ksb = kvB + st * 16384;
        const unsigned vsb = ksb + 8192;

        float sc[8][4];
        #pragma unroll
        for (int nd = 0; nd < 8; nd++) {
            sc[nd][0] = sc[nd][1] = sc[nd][2] = sc[nd][3] = 0.f;
            const int row = nd * 8 + lr;
            uint4 kh, kl;
            ldsm4(kh, ksb + swz(row, lm) * 16);
            ldsm4(kl, ksb + swz(row, lm + 4) * 16);
            mma_bf16(sc[nd], aqh[0], kh.x, kh.y);
            mma_bf16(sc[nd], aqh[1], kh.z, kh.w);
            mma_bf16(sc[nd], aqh[0], kl.x, kl.y);
            mma_bf16(sc[nd], aqh[1], kl.z, kl.w);
            mma_bf16(sc[nd], aql[0], kh.x, kh.y);
            mma_bf16(sc[nd], aql[1], kh.z, kh.w);
        }

        float t0 = -1e30f, t1 = -1e30f;
        #pragma unroll
        for (int nd = 0; nd < 8; nd++) {
            t0 = fmaxf(t0, fmaxf(sc[nd][0], sc[nd][1]));
            t1 = fmaxf(t1, fmaxf(sc[nd][2], sc[nd][3]));
        }
        t0 = fmaxf(t0, __shfl_xor_sync(0xffffffffu, t0, 1));
        t0 = fmaxf(t0, __shfl_xor_sync(0xffffffffu, t0, 2));
        t1 = fmaxf(t1, __shfl_xor_sync(0xffffffffu, t1, 1));
        t1 = fmaxf(t1, __shfl_xor_sync(0xffffffffu, t1, 2));

        const float nm0 = fmaxf(m0, t0);
        const float nm1 = fmaxf(m1, t1);
        const float c0  = ex2f(m0 - nm0);
        const float c1  = ex2f(m1 - nm1);

        float rs0 = 0.f, rs1 = 0.f;
        #pragma unroll
        for (int nd = 0; nd < 8; nd++) {
            sc[nd][0] = ex2f(sc[nd][0] - nm0);
            sc[nd][1] = ex2f(sc[nd][1] - nm0);
            sc[nd][2] = ex2f(sc[nd][2] - nm1);
            sc[nd][3] = ex2f(sc[nd][3] - nm1);
            rs0 += sc[nd][0] + sc[nd][1];
            rs1 += sc[nd][2] + sc[nd][3];
        }
        rs0 += __shfl_xor_sync(0xffffffffu, rs0, 1);
        rs0 += __shfl_xor_sync(0xffffffffu, rs0, 2);
        rs1 += __shfl_xor_sync(0xffffffffu, rs1, 1);
        rs1 += __shfl_xor_sync(0xffffffffu, rs1, 2);

        l0 = l0 * c0 + rs0;
        l1 = l1 * c1 + rs1;
        #pragma unroll
        for (int nd = 0; nd < 4; nd++) {
            o[nd][0] *= c0; o[nd][1] *= c0;
            o[nd][2] *= c1; o[nd][3] *= c1;
        }
        m0 = nm0; m1 = nm1;

        #pragma unroll
        for (int kb = 0; kb < 4; kb++) {
            unsigned ph[4], pl[4];
            bsplit2(sc[2 * kb][0],     sc[2 * kb][1],     ph[0], pl[0]);
            bsplit2(sc[2 * kb][2],     sc[2 * kb][3],     ph[1], pl[1]);
            bsplit2(sc[2 * kb + 1][0], sc[2 * kb + 1][1], ph[2], pl[2]);
            bsplit2(sc[2 * kb + 1][2], sc[2 * kb + 1][3], ph[3], pl[3]);
            #pragma unroll
            for (int dp = 0; dp < 2; dp++) {
                const int row = kb * 16 + ((lm & 1) << 3) + lr;
                const int u   = dp * 2 + (lm >> 1);
                uint4 vh, vl;
                ldsm4t(vh, vsb + swz(row, u) * 16);
                ldsm4t(vl, vsb + swz(row, u + 4) * 16);
                mma_bf16(o[2 * dp],     ph, vh.x, vh.y);
                mma_bf16(o[2 * dp],     ph, vl.x, vl.y);
                mma_bf16(o[2 * dp],     pl, vh.x, vh.y);
                mma_bf16(o[2 * dp + 1], ph, vh.z, vh.w);
                mma_bf16(o[2 * dp + 1], ph, vl.z, vl.w);
                mma_bf16(o[2 * dp + 1], pl, vh.z, vh.w);
            }
        }

        st = (st + 1 == 3) ? 0 : st + 1;
    }

    // ---- epilogue: write O in gemm<1>'s A-tile image (bf16 hi/lo) ----
    const float i0 = 1.0f / l0;
    const float i1 = 1.0f / l1;
    const int n = nh >> 4;
    unsigned* Ow = (unsigned*)g_Ob;
    #pragma unroll
    for (int rh = 0; rh < 2; rh++) {
        const int r = (q0 + g + rh * 8) * NB + n;
        const unsigned base = (unsigned)(h * 64 + (r >> 7)) * 1024;
        const int rowc = r & 127;
        const float inv = rh ? i1 : i0;
        #pragma unroll
        for (int nd = 0; nd < 4; nd++) {
            unsigned hi, lo;
            bsplit2(o[nd][rh * 2] * inv, o[nd][rh * 2 + 1] * inv, hi, lo);
            Ow[(base + swz(rowc, nd)) * 4 + t]     = hi;
            Ow[(base + swz(rowc, nd + 4)) * 4 + t] = lo;
        }
    }
}

// ---------------------------------------------------------------------------
extern "C" void kernel_launch(void* const* d_in, const int* in_sizes, int n_in,
                              void* d_out, int out_size)
{
    const float* query   = (const float*)d_in[0];
    const float* key_in  = (const float*)d_in[1];
    const float* value   = (const float*)d_in[2];
    const float* scaling = (const float*)d_in[3];
    const float* in_w    = (const float*)d_in[4];
    const float* in_b    = (const float*)d_in[5];
    const float* pn_w    = (const float*)d_in[6];
    const float* pn_b    = (const float*)d_in[7];
    const float* out_w   = (const float*)d_in[8];
    const float* out_b   = (const float*)d_in[9];
    float* out = (float*)d_out;

    // 0) weights + inputs -> bf16 hi/lo swizzled images
    prep_w_kernel<<<dim3(16, 8, 4), 256>>>(in_w, out_w);
    prep_x_kernel<<<dim3(16, 64, 3), 256>>>(query, key_in, value);

    // 1) QKV projections (+LN for K/V, +beta*log2e for Q) -> split images
    gemm_mma_kernel<0><<<dim3(ROWS / 128, EMB / 64, 3), 256>>>(
        in_b, nullptr, pn_w, pn_b, scaling);

    // 2) Flash attention -> O split image
    attn_mma_kernel<<<dim3(LQ / 128, NB * NH), 256>>>();

    // 3) Output projection -> d_out
    gemm_mma_kernel<1><<<dim3(ROWS / 128, EMB / 64, 1), 256>>>(
        out_b, out, nullptr, nullptr, nullptr);
}

// round 16
// speedup vs baseline: 2.9459x; 1.1337x over previous
#include <cuda_runtime.h>
#include <cuda_fp16.h>

#define LQ  2048
#define SK  2048
#define NB  4
#define EMB 512
#define NH  16
#define HD  32
#define ROWS (LQ * NB)   // 8192

// ---------------------------------------------------------------------------
// Global scratch: everything fp16 hi/lo, pre-swizzled smem images.
//  Q/K/V: [nh(64)][chunk(32)][512 uint4]   (64 rows x 8 units, swz layout)
//  O:     [e-chunk(16)][row-block(64)][1024 uint4] (128 rows x 8 units)
//  W:     [z(4)][n-block(8)][k-chunk(16)][512 uint4]
//  I:     [z(3)][k-chunk(16)][row-block(64)][1024 uint4]  (converted inputs)
// ---------------------------------------------------------------------------
__device__ uint4 g_Qb[64 * 32 * 512];
__device__ uint4 g_Kb[64 * 32 * 512];
__device__ uint4 g_Vb[64 * 32 * 512];
__device__ uint4 g_Ob[16 * 64 * 1024];
__device__ uint4 g_Wb[4 * 8 * 16 * 512];
__device__ uint4 g_Ib[3 * 16 * 64 * 1024];

// ---------------------------------------------------------------------------
// helpers
// ---------------------------------------------------------------------------
__device__ __forceinline__ void mma_f16(float* c, const unsigned* a,
                                        unsigned b0, unsigned b1) {
    asm volatile(
        "mma.sync.aligned.m16n8k16.row.col.f32.f16.f16.f32 "
        "{%0,%1,%2,%3}, {%4,%5,%6,%7}, {%8,%9}, {%0,%1,%2,%3};"
        : "+f"(c[0]), "+f"(c[1]), "+f"(c[2]), "+f"(c[3])
        : "r"(a[0]), "r"(a[1]), "r"(a[2]), "r"(a[3]), "r"(b0), "r"(b1));
}
__device__ __forceinline__ unsigned hpack2(float x, float y) {
    __half2 h = __floats2half2_rn(x, y);
    return *reinterpret_cast<unsigned*>(&h);
}
__device__ __forceinline__ void hsplit2(float x, float y, unsigned &hi, unsigned &lo) {
    __half2 h = __floats2half2_rn(x, y);
    const float hx = __low2float(h);
    const float hy = __high2float(h);
    __half2 l = __floats2half2_rn(x - hx, y - hy);
    hi = *reinterpret_cast<unsigned*>(&h);
    lo = *reinterpret_cast<unsigned*>(&l);
}
__device__ __forceinline__ void pack8(const float4 a, const float4 b,
                                      uint4 &hi, uint4 &lo) {
    hsplit2(a.x, a.y, hi.x, lo.x);
    hsplit2(a.z, a.w, hi.y, lo.y);
    hsplit2(b.x, b.y, hi.z, lo.z);
    hsplit2(b.z, b.w, hi.w, lo.w);
}
__device__ __forceinline__ void ldsm4(uint4 &d, unsigned addr) {
    asm volatile("ldmatrix.sync.aligned.m8n8.x4.shared.b16 {%0,%1,%2,%3}, [%4];"
                 : "=r"(d.x), "=r"(d.y), "=r"(d.z), "=r"(d.w) : "r"(addr));
}
__device__ __forceinline__ void ldsm4t(uint4 &d, unsigned addr) {
    asm volatile("ldmatrix.sync.aligned.m8n8.x4.trans.shared.b16 {%0,%1,%2,%3}, [%4];"
                 : "=r"(d.x), "=r"(d.y), "=r"(d.z), "=r"(d.w) : "r"(addr));
}
__device__ __forceinline__ int swz(int row, int u) {
    return row * 8 + (u ^ (row & 7));
}
__device__ __forceinline__ float ex2f(float x) {
    float y;
    asm("ex2.approx.ftz.f32 %0, %1;" : "=f"(y) : "f"(x));
    return y;
}
__device__ __forceinline__ unsigned smem_u32(const void* p) {
    return (unsigned)__cvta_generic_to_shared(p);
}
__device__ __forceinline__ void cpa16(unsigned dst, const void* src) {
    asm volatile("cp.async.cg.shared.global [%0], [%1], 16;" :: "r"(dst), "l"(src));
}
#define CPA_COMMIT() asm volatile("cp.async.commit_group;" ::: "memory")
#define CPA_WAIT(n)  asm volatile("cp.async.wait_group %0;" :: "n"(n) : "memory")

// ---------------------------------------------------------------------------
// Weight prep: fp32 -> fp16 hi/lo, swizzled tile images. grid (16, 8, 4).
// ---------------------------------------------------------------------------
__global__ __launch_bounds__(256)
void prep_w_kernel(const float* __restrict__ in_w, const float* __restrict__ out_w)
{
    const int c  = blockIdx.x;
    const int nb = blockIdx.y;
    const int z  = blockIdx.z;
    const int tid = threadIdx.x;
    const int row  = tid >> 2;
    const int colB = (tid & 3) * 8;
    const float* Wsrc = (z < 3) ? (in_w + (size_t)z * EMB * EMB) : out_w;
    const float* p = Wsrc + (size_t)(nb * 64 + row) * EMB + c * 32 + colB;
    uint4 hi, lo;
    pack8(*(const float4*)p, *(const float4*)(p + 4), hi, lo);
    uint4* base = g_Wb + (size_t)((z * 8 + nb) * 16 + c) * 512;
    base[swz(row, colB >> 3)]       = hi;
    base[swz(row, (colB >> 3) + 4)] = lo;
}

// ---------------------------------------------------------------------------
// Input prep: query/key_in/value fp32 -> fp16 hi/lo A-tile images.
// grid (16 k-chunks, 64 row-blocks, 3), 256 thr.
// ---------------------------------------------------------------------------
__global__ __launch_bounds__(256)
void prep_x_kernel(const float* __restrict__ q, const float* __restrict__ k,
                   const float* __restrict__ v)
{
    const int c  = blockIdx.x;
    const int rb = blockIdx.y;
    const int z  = blockIdx.z;
    const int tid = threadIdx.x;
    const int row  = tid >> 1;
    const int colA = (tid & 1) * 16;
    const float* X = (z == 0) ? q : (z == 1) ? k : v;
    const float* p = X + (size_t)(rb * 128 + row) * EMB + c * 32 + colA;
    uint4* img = g_Ib + (size_t)((z * 16 + c) * 64 + rb) * 1024;
    const int u = colA >> 3;
    uint4 hi, lo;
    pack8(*(const float4*)p, *(const float4*)(p + 4), hi, lo);
    img[swz(row, u)]     = hi;
    img[swz(row, u + 4)] = lo;
    pack8(*(const float4*)(p + 8), *(const float4*)(p + 12), hi, lo);
    img[swz(row, u + 1)] = hi;
    img[swz(row, u + 5)] = lo;
}

// ---------------------------------------------------------------------------
// 3xFP16 GEMM. Block 128x64, BK=32, 256 thr (8 warps 4Mx2N), warptile 32x32.
// A and B both stream via cp.async from pre-split images (g_Ib/g_Ob, g_Wb).
// MODE 0 epilogue: Q (beta*log2e folded) / K,V (LayerNorm) -> split images.
// MODE 1 epilogue: fp32 + bias -> d_out.
// ---------------------------------------------------------------------------
template<int MODE>
__global__ __launch_bounds__(256)
void gemm_mma_kernel(const float* __restrict__ bfull, float* __restrict__ outp,
                     const float* __restrict__ pnw, const float* __restrict__ pnb,
                     const float* __restrict__ scaling)
{
    __shared__ uint4 ASm[2][1024];   // 32KB
    __shared__ uint4 BSm[2][512];    // 16KB

    const int tid    = threadIdx.x;
    const int warp   = tid >> 5;
    const int lane   = tid & 31;
    const int g      = lane >> 2;
    const int t      = lane & 3;
    const int warp_m = warp >> 1;
    const int warp_n = warp & 1;
    const int r0     = blockIdx.x * 128;
    const int f0     = blockIdx.y * 64;

    const int zW = (MODE == 0) ? blockIdx.z : 3;
    const uint4* Wt   = g_Wb + (size_t)(zW * 8 + blockIdx.y) * 16 * 512;
    const uint4* Aimg = (MODE == 0) ? (g_Ib + (size_t)blockIdx.z * 16 * 64 * 1024)
                                    : g_Ob;
    const float* bias = (MODE == 0) ? bfull + blockIdx.z * EMB : bfull;

    const unsigned aBase = smem_u32(ASm);
    const unsigned bBase = smem_u32(BSm);
    const int lm = lane >> 3;
    const int lr = lane & 7;

    float acc[2][4][4];
    #pragma unroll
    for (int mi = 0; mi < 2; mi++)
        #pragma unroll
        for (int ni = 0; ni < 4; ni++)
            #pragma unroll
            for (int j = 0; j < 4; j++) acc[mi][ni][j] = 0.f;

    // ---- prologue: chunk 0 ----
    {
        const uint4* Asrc = Aimg + (size_t)blockIdx.x * 1024;
        #pragma unroll
        for (int k = 0; k < 4; k++)
            cpa16(aBase + (tid + k * 256) * 16, Asrc + tid + k * 256);
        cpa16(bBase + tid * 16, Wt + tid);
        cpa16(bBase + (tid + 256) * 16, Wt + tid + 256);
        CPA_COMMIT();
    }

    for (int c = 0; c < 16; c++) {
        const int cur = c & 1, nxt = cur ^ 1;
        CPA_WAIT(0);
        __syncthreads();
        if (c + 1 < 16) {
            const uint4* Asrc = Aimg + (size_t)((c + 1) * 64 + blockIdx.x) * 1024;
            #pragma unroll
            for (int k = 0; k < 4; k++)
                cpa16(aBase + (nxt * 1024 + tid + k * 256) * 16, Asrc + tid + k * 256);
            const uint4* Bsrc = Wt + (size_t)(c + 1) * 512;
            cpa16(bBase + (nxt * 512 + tid) * 16, Bsrc + tid);
            cpa16(bBase + (nxt * 512 + tid + 256) * 16, Bsrc + tid + 256);
            CPA_COMMIT();
        }

        const unsigned aOff = aBase + cur * (1024 * 16);
        const unsigned bOff = bBase + cur * (512 * 16);
        #pragma unroll
        for (int ks = 0; ks < 2; ks++) {
            uint4 ah[2], al[2], bh[2], bl[2];
            #pragma unroll
            for (int mi = 0; mi < 2; mi++) {
                const int row = warp_m * 32 + mi * 16 + ((lm & 1) << 3) + lr;
                const int u   = ks * 2 + (lm >> 1);
                ldsm4(ah[mi], aOff + swz(row, u) * 16);
                ldsm4(al[mi], aOff + swz(row, u + 4) * 16);
            }
            #pragma unroll
            for (int bi = 0; bi < 2; bi++) {
                const int row = warp_n * 32 + bi * 16 + ((lm >> 1) << 3) + lr;
                const int u   = ks * 2 + (lm & 1);
                ldsm4(bh[bi], bOff + swz(row, u) * 16);
                ldsm4(bl[bi], bOff + swz(row, u + 4) * 16);
            }
            #pragma unroll
            for (int ni = 0; ni < 4; ni++) {
                const int bi = ni >> 1;
                const unsigned h0 = (ni & 1) ? bh[bi].z : bh[bi].x;
                const unsigned h1 = (ni & 1) ? bh[bi].w : bh[bi].y;
                const unsigned l0 = (ni & 1) ? bl[bi].z : bl[bi].x;
                const unsigned l1 = (ni & 1) ? bl[bi].w : bl[bi].y;
                #pragma unroll
                for (int mi = 0; mi < 2; mi++) {
                    mma_f16(acc[mi][ni], &ah[mi].x, h0, h1);
                    mma_f16(acc[mi][ni], &ah[mi].x, l0, l1);
                    mma_f16(acc[mi][ni], &al[mi].x, h0, h1);
                }
            }
        }
    }

    // ---- epilogue ----
    if (MODE == 0) {
        const int z = blockIdx.z;
        const int h = (f0 + warp_n * 32) >> 5;
        unsigned* dw = (unsigned*)((z == 0) ? g_Qb : (z == 1) ? g_Kb : g_Vb);
        const bool doLN = (z != 0);
        const float qscale = doLN ? 1.0f : scaling[h] * 1.4426950408889634f;
        float pwv[8], pbv[8];
        if (doLN) {
            #pragma unroll
            for (int ni = 0; ni < 4; ni++) {
                const int d = ni * 8 + 2 * t;
                pwv[ni * 2]     = pnw[d];
                pwv[ni * 2 + 1] = pnw[d + 1];
                pbv[ni * 2]     = pnb[d];
                pbv[ni * 2 + 1] = pnb[d + 1];
            }
        }
        #pragma unroll
        for (int mi = 0; mi < 2; mi++) {
            float vals[2][8];
            #pragma unroll
            for (int ni = 0; ni < 4; ni++) {
                const int f = f0 + warp_n * 32 + ni * 8 + 2 * t;
                const float b0 = bias[f];
                const float b1 = bias[f + 1];
                vals[0][ni * 2]     = acc[mi][ni][0] + b0;
                vals[0][ni * 2 + 1] = acc[mi][ni][1] + b1;
                vals[1][ni * 2]     = acc[mi][ni][2] + b0;
                vals[1][ni * 2 + 1] = acc[mi][ni][3] + b1;
            }
            #pragma unroll
            for (int rh = 0; rh < 2; rh++) {
                if (doLN) {
                    float s = 0.f, s2 = 0.f;
                    #pragma unroll
                    for (int j = 0; j < 8; j++) {
                        s  += vals[rh][j];
                        s2 += vals[rh][j] * vals[rh][j];
                    }
                    s  += __shfl_xor_sync(0xffffffffu, s, 1);
                    s  += __shfl_xor_sync(0xffffffffu, s, 2);
                    s2 += __shfl_xor_sync(0xffffffffu, s2, 1);
                    s2 += __shfl_xor_sync(0xffffffffu, s2, 2);
                    const float mu  = s * (1.0f / HD);
                    const float var = s2 * (1.0f / HD) - mu * mu;
                    const float inv = rsqrtf(var + 1e-5f);
                    #pragma unroll
                    for (int j = 0; j < 8; j++)
                        vals[rh][j] = (vals[rh][j] - mu) * inv * pwv[j] + pbv[j];
                } else {
                    #pragma unroll
                    for (int j = 0; j < 8; j++) vals[rh][j] *= qscale;
                }
                const int r = r0 + warp_m * 32 + mi * 16 + g + rh * 8;
                const int l = r >> 2, n = r & 3;
                const unsigned base = ((unsigned)(n * NH + h) * 32 + (l >> 6)) * 512;
                const int rowc = l & 63;
                #pragma unroll
                for (int ni = 0; ni < 4; ni++) {
                    unsigned hi, lo;
                    hsplit2(vals[rh][ni * 2], vals[rh][ni * 2 + 1], hi, lo);
                    dw[(base + swz(rowc, ni)) * 4 + t]     = hi;
                    dw[(base + swz(rowc, ni + 4)) * 4 + t] = lo;
                }
            }
        }
    } else {
        #pragma unroll
        for (int mi = 0; mi < 2; mi++) {
            const int rA = r0 + warp_m * 32 + mi * 16 + g;
            const int rB = rA + 8;
            #pragma unroll
            for (int ni = 0; ni < 4; ni++) {
                const float* c = acc[mi][ni];
                const int f  = f0 + warp_n * 32 + ni * 8 + 2 * t;
                const float b0 = bias[f];
                const float b1 = bias[f + 1];
                *(float2*)(outp + (size_t)rA * EMB + f) = make_float2(c[0] + b0, c[1] + b1);
                *(float2*)(outp + (size_t)rB * EMB + f) = make_float2(c[2] + b0, c[3] + b1);
            }
        }
    }
}

// ---------------------------------------------------------------------------
// Flash attention: pre-split fp16 hi/lo operands, ring-3 cp.async K/V.
// QK = Qh*Kh + Qh*Kl + Ql*Kh (fp32-level scores).
// PV = Ph*Vh + Ph*Vl        (V exact; P rounded once at 2^-11).
// Softmax via ex2.approx. Block 256 thr (8 warps), 16 q rows/warp,
// S-chunks of 64, grid (16, 64).
// ---------------------------------------------------------------------------
__global__ __launch_bounds__(256)
void attn_mma_kernel()
{
    __shared__ uint4 KV[3][1024];   // [stage][K 0..511 | V 512..1023], 48KB

    const int tid  = threadIdx.x;
    const int warp = tid >> 5;
    const int lane = tid & 31;
    const int g    = lane >> 2;
    const int t    = lane & 3;
    const int nh   = blockIdx.y;
    const int h    = nh & (NH - 1);
    const int q0   = blockIdx.x * 128 + warp * 16;

    const unsigned kvB = smem_u32(KV);
    const int lm = lane >> 3;
    const int lr = lane & 7;

    // Q fragments straight from the split image
    const unsigned* Qw = (const unsigned*)g_Qb;
    const unsigned qbase = ((unsigned)nh * 32 + (q0 >> 6)) * 512;
    const int rc = q0 & 63;
    unsigned aqh[2][4], aql[2][4];
    #pragma unroll
    for (int ks = 0; ks < 2; ks++) {
        aqh[ks][0] = Qw[(qbase + swz(rc + g,     2 * ks)) * 4 + t];
        aqh[ks][1] = Qw[(qbase + swz(rc + g + 8, 2 * ks)) * 4 + t];
        aqh[ks][2] = Qw[(qbase + swz(rc + g,     2 * ks + 1)) * 4 + t];
        aqh[ks][3] = Qw[(qbase + swz(rc + g + 8, 2 * ks + 1)) * 4 + t];
        aql[ks][0] = Qw[(qbase + swz(rc + g,     2 * ks + 4)) * 4 + t];
        aql[ks][1] = Qw[(qbase + swz(rc + g + 8, 2 * ks + 4)) * 4 + t];
        aql[ks][2] = Qw[(qbase + swz(rc + g,     2 * ks + 5)) * 4 + t];
        aql[ks][3] = Qw[(qbase + swz(rc + g + 8, 2 * ks + 5)) * 4 + t];
    }

    float m0 = -1e30f, m1 = -1e30f, l0 = 0.f, l1 = 0.f;
    float o[4][4];
    #pragma unroll
    for (int nd = 0; nd < 4; nd++)
        #pragma unroll
        for (int j = 0; j < 4; j++) o[nd][j] = 0.f;

    const uint4* Ksrc = g_Kb + (size_t)nh * 32 * 512;
    const uint4* Vsrc = g_Vb + (size_t)nh * 32 * 512;

    cpa16(kvB + tid * 16,               Ksrc + tid);
    cpa16(kvB + (tid + 256) * 16,       Ksrc + tid + 256);
    cpa16(kvB + (512 + tid) * 16,       Vsrc + tid);
    cpa16(kvB + (512 + tid + 256) * 16, Vsrc + tid + 256);
    CPA_COMMIT();

    int st = 0;
    for (int c = 0; c < 32; c++) {
        if (c + 1 < 32) {
            const int ns = (st + 1 == 3) ? 0 : st + 1;
            const unsigned dB = kvB + ns * 16384;
            const uint4* Kc = Ksrc + (size_t)(c + 1) * 512;
            const uint4* Vc = Vsrc + (size_t)(c + 1) * 512;
            cpa16(dB + tid * 16,               Kc + tid);
            cpa16(dB + (tid + 256) * 16,       Kc + tid + 256);
            cpa16(dB + (512 + tid) * 16,       Vc + tid);
            cpa16(dB + (512 + tid + 256) * 16, Vc + tid + 256);
            CPA_COMMIT();
            CPA_WAIT(1);
        } else {
            CPA_WAIT(0);
        }
        __syncthreads();

        const unsigned ksb = kvB + st * 16384;
        const unsigned vsb = ksb + 8192;

        // ---- QK scores (3xFP16): 8 s-tiles of 16x8 ----
        float sc[8][4];
        #pragma unroll
        for (int nd = 0; nd < 8; nd++) {
            sc[nd][0] = sc[nd][1] = sc[nd][2] = sc[nd][3] = 0.f;
            const int row = nd * 8 + lr;
            uint4 kh, kl;
            ldsm4(kh, ksb + swz(row, lm) * 16);
            ldsm4(kl, ksb + swz(row, lm + 4) * 16);
            mma_f16(sc[nd], aqh[0], kh.x, kh.y);
            mma_f16(sc[nd], aqh[1], kh.z, kh.w);
            mma_f16(sc[nd], aqh[0], kl.x, kl.y);
            mma_f16(sc[nd], aqh[1], kl.z, kl.w);
            mma_f16(sc[nd], aql[0], kh.x, kh.y);
            mma_f16(sc[nd], aql[1], kh.z, kh.w);
        }

        // ---- online softmax (exp2 domain) ----
        float t0 = -1e30f, t1 = -1e30f;
        #pragma unroll
        for (int nd = 0; nd < 8; nd++) {
            t0 = fmaxf(t0, fmaxf(sc[nd][0], sc[nd][1]));
            t1 = fmaxf(t1, fmaxf(sc[nd][2], sc[nd][3]));
        }
        t0 = fmaxf(t0, __shfl_xor_sync(0xffffffffu, t0, 1));
        t0 = fmaxf(t0, __shfl_xor_sync(0xffffffffu, t0, 2));
        t1 = fmaxf(t1, __shfl_xor_sync(0xffffffffu, t1, 1));
        t1 = fmaxf(t1, __shfl_xor_sync(0xffffffffu, t1, 2));

        const float nm0 = fmaxf(m0, t0);
        const float nm1 = fmaxf(m1, t1);
        const float c0  = ex2f(m0 - nm0);
        const float c1  = ex2f(m1 - nm1);

        float rs0 = 0.f, rs1 = 0.f;
        #pragma unroll
        for (int nd = 0; nd < 8; nd++) {
            sc[nd][0] = ex2f(sc[nd][0] - nm0);
            sc[nd][1] = ex2f(sc[nd][1] - nm0);
            sc[nd][2] = ex2f(sc[nd][2] - nm1);
            sc[nd][3] = ex2f(sc[nd][3] - nm1);
            rs0 += sc[nd][0] + sc[nd][1];
            rs1 += sc[nd][2] + sc[nd][3];
        }
        rs0 += __shfl_xor_sync(0xffffffffu, rs0, 1);
        rs0 += __shfl_xor_sync(0xffffffffu, rs0, 2);
        rs1 += __shfl_xor_sync(0xffffffffu, rs1, 1);
        rs1 += __shfl_xor_sync(0xffffffffu, rs1, 2);

        l0 = l0 * c0 + rs0;
        l1 = l1 * c1 + rs1;
        #pragma unroll
        for (int nd = 0; nd < 4; nd++) {
            o[nd][0] *= c0; o[nd][1] *= c0;
            o[nd][2] *= c1; o[nd][3] *= c1;
        }
        m0 = nm0; m1 = nm1;

        // ---- PV (2xFP16): P packed once (single cvt), V hi+lo ----
        #pragma unroll
        for (int kb = 0; kb < 4; kb++) {
            unsigned ph[4];
            ph[0] = hpack2(sc[2 * kb][0],     sc[2 * kb][1]);
            ph[1] = hpack2(sc[2 * kb][2],     sc[2 * kb][3]);
            ph[2] = hpack2(sc[2 * kb + 1][0], sc[2 * kb + 1][1]);
            ph[3] = hpack2(sc[2 * kb + 1][2], sc[2 * kb + 1][3]);
            #pragma unroll
            for (int dp = 0; dp < 2; dp++) {
                const int row = kb * 16 + ((lm & 1) << 3) + lr;
                const int u   = dp * 2 + (lm >> 1);
                uint4 vh, vl;
                ldsm4t(vh, vsb + swz(row, u) * 16);
                ldsm4t(vl, vsb + swz(row, u + 4) * 16);
                mma_f16(o[2 * dp],     ph, vh.x, vh.y);
                mma_f16(o[2 * dp],     ph, vl.x, vl.y);
                mma_f16(o[2 * dp + 1], ph, vh.z, vh.w);
                mma_f16(o[2 * dp + 1], ph, vl.z, vl.w);
            }
        }

        st = (st + 1 == 3) ? 0 : st + 1;
    }

    // ---- epilogue: write O in gemm<1>'s A-tile image (fp16 hi/lo) ----
    const float i0 = 1.0f / l0;
    const float i1 = 1.0f / l1;
    const int n = nh >> 4;
    unsigned* Ow = (unsigned*)g_Ob;
    #pragma unroll
    for (int rh = 0; rh < 2; rh++) {
        const int r = (q0 + g + rh * 8) * NB + n;
        const unsigned base = (unsigned)(h * 64 + (r >> 7)) * 1024;
        const int rowc = r & 127;
        const float inv = rh ? i1 : i0;
        #pragma unroll
        for (int nd = 0; nd < 4; nd++) {
            unsigned hi, lo;
            hsplit2(o[nd][rh * 2] * inv, o[nd][rh * 2 + 1] * inv, hi, lo);
            Ow[(base + swz(rowc, nd)) * 4 + t]     = hi;
            Ow[(base + swz(rowc, nd + 4)) * 4 + t] = lo;
        }
    }
}

// ---------------------------------------------------------------------------
extern "C" void kernel_launch(void* const* d_in, const int* in_sizes, int n_in,
                              void* d_out, int out_size)
{
    const float* query   = (const float*)d_in[0];
    const float* key_in  = (const float*)d_in[1];
    const float* value   = (const float*)d_in[2];
    const float* scaling = (const float*)d_in[3];
    const float* in_w    = (const float*)d_in[4];
    const float* in_b    = (const float*)d_in[5];
    const float* pn_w    = (const float*)d_in[6];
    const float* pn_b    = (const float*)d_in[7];
    const float* out_w   = (const float*)d_in[8];
    const float* out_b   = (const float*)d_in[9];
    float* out = (float*)d_out;

    // 0) weights + inputs -> fp16 hi/lo swizzled images
    prep_w_kernel<<<dim3(16, 8, 4), 256>>>(in_w, out_w);
    prep_x_kernel<<<dim3(16, 64, 3), 256>>>(query, key_in, value);

    // 1) QKV projections (+LN for K/V, +beta*log2e for Q) -> split images
    gemm_mma_kernel<0><<<dim3(ROWS / 128, EMB / 64, 3), 256>>>(
        in_b, nullptr, pn_w, pn_b, scaling);

    // 2) Flash attention -> O split image
    attn_mma_kernel<<<dim3(LQ / 128, NB * NH), 256>>>();

    // 3) Output projection -> d_out
    gemm_mma_kernel<1><<<dim3(ROWS / 128, EMB / 64, 1), 256>>>(
        out_b, out, nullptr, nullptr, nullptr);
}

// round 17
// speedup vs baseline: 3.1998x; 1.0862x over previous
#include <cuda_runtime.h>
#include <cuda_fp16.h>

#define LQ  2048
#define SK  2048
#define NB  4
#define EMB 512
#define NH  16
#define HD  32
#define ROWS (LQ * NB)   // 8192

// ---------------------------------------------------------------------------
// Global scratch: everything fp16 hi/lo, pre-swizzled smem images.
//  Q/K/V: [nh(64)][chunk(32)][512 uint4]   (64 rows x 8 units, swz layout)
//  O:     [e-chunk(16)][row-block(64)][1024 uint4] (128 rows x 8 units)
//  W:     [z(4)][n-block(8)][k-chunk(16)][512 uint4]
//  I:     [z(3)][k-chunk(16)][row-block(64)][1024 uint4]  (converted inputs)
// ---------------------------------------------------------------------------
__device__ uint4 g_Qb[64 * 32 * 512];
__device__ uint4 g_Kb[64 * 32 * 512];
__device__ uint4 g_Vb[64 * 32 * 512];
__device__ uint4 g_Ob[16 * 64 * 1024];
__device__ uint4 g_Wb[4 * 8 * 16 * 512];
__device__ uint4 g_Ib[3 * 16 * 64 * 1024];

// ---------------------------------------------------------------------------
// helpers
// ---------------------------------------------------------------------------
__device__ __forceinline__ void mma_f16(float* c, const unsigned* a,
                                        unsigned b0, unsigned b1) {
    asm volatile(
        "mma.sync.aligned.m16n8k16.row.col.f32.f16.f16.f32 "
        "{%0,%1,%2,%3}, {%4,%5,%6,%7}, {%8,%9}, {%0,%1,%2,%3};"
        : "+f"(c[0]), "+f"(c[1]), "+f"(c[2]), "+f"(c[3])
        : "r"(a[0]), "r"(a[1]), "r"(a[2]), "r"(a[3]), "r"(b0), "r"(b1));
}
__device__ __forceinline__ unsigned hpack2(float x, float y) {
    __half2 h = __floats2half2_rn(x, y);
    return *reinterpret_cast<unsigned*>(&h);
}
__device__ __forceinline__ void hsplit2(float x, float y, unsigned &hi, unsigned &lo) {
    __half2 h = __floats2half2_rn(x, y);
    const float hx = __low2float(h);
    const float hy = __high2float(h);
    __half2 l = __floats2half2_rn(x - hx, y - hy);
    hi = *reinterpret_cast<unsigned*>(&h);
    lo = *reinterpret_cast<unsigned*>(&l);
}
__device__ __forceinline__ void pack8(const float4 a, const float4 b,
                                      uint4 &hi, uint4 &lo) {
    hsplit2(a.x, a.y, hi.x, lo.x);
    hsplit2(a.z, a.w, hi.y, lo.y);
    hsplit2(b.x, b.y, hi.z, lo.z);
    hsplit2(b.z, b.w, hi.w, lo.w);
}
__device__ __forceinline__ void ldsm4(uint4 &d, unsigned addr) {
    asm volatile("ldmatrix.sync.aligned.m8n8.x4.shared.b16 {%0,%1,%2,%3}, [%4];"
                 : "=r"(d.x), "=r"(d.y), "=r"(d.z), "=r"(d.w) : "r"(addr));
}
__device__ __forceinline__ void ldsm4t(uint4 &d, unsigned addr) {
    asm volatile("ldmatrix.sync.aligned.m8n8.x4.trans.shared.b16 {%0,%1,%2,%3}, [%4];"
                 : "=r"(d.x), "=r"(d.y), "=r"(d.z), "=r"(d.w) : "r"(addr));
}
__device__ __forceinline__ int swz(int row, int u) {
    return row * 8 + (u ^ (row & 7));
}
__device__ __forceinline__ float ex2f(float x) {
    float y;
    asm("ex2.approx.ftz.f32 %0, %1;" : "=f"(y) : "f"(x));
    return y;
}
__device__ __forceinline__ unsigned smem_u32(const void* p) {
    return (unsigned)__cvta_generic_to_shared(p);
}
__device__ __forceinline__ void cpa16(unsigned dst, const void* src) {
    asm volatile("cp.async.cg.shared.global [%0], [%1], 16;" :: "r"(dst), "l"(src));
}
#define CPA_COMMIT() asm volatile("cp.async.commit_group;" ::: "memory")
#define CPA_WAIT(n)  asm volatile("cp.async.wait_group %0;" :: "n"(n) : "memory")

// ---------------------------------------------------------------------------
// Weight prep: fp32 -> fp16 hi/lo, swizzled tile images. grid (16, 8, 4).
// ---------------------------------------------------------------------------
__global__ __launch_bounds__(256)
void prep_w_kernel(const float* __restrict__ in_w, const float* __restrict__ out_w)
{
    const int c  = blockIdx.x;
    const int nb = blockIdx.y;
    const int z  = blockIdx.z;
    const int tid = threadIdx.x;
    const int row  = tid >> 2;
    const int colB = (tid & 3) * 8;
    const float* Wsrc = (z < 3) ? (in_w + (size_t)z * EMB * EMB) : out_w;
    const float* p = Wsrc + (size_t)(nb * 64 + row) * EMB + c * 32 + colB;
    uint4 hi, lo;
    pack8(*(const float4*)p, *(const float4*)(p + 4), hi, lo);
    uint4* base = g_Wb + (size_t)((z * 8 + nb) * 16 + c) * 512;
    base[swz(row, colB >> 3)]       = hi;
    base[swz(row, (colB >> 3) + 4)] = lo;
}

// ---------------------------------------------------------------------------
// Input prep: query/key_in/value fp32 -> fp16 hi/lo A-tile images.
// grid (16 k-chunks, 64 row-blocks, 3), 256 thr.
// ---------------------------------------------------------------------------
__global__ __launch_bounds__(256)
void prep_x_kernel(const float* __restrict__ q, const float* __restrict__ k,
                   const float* __restrict__ v)
{
    const int c  = blockIdx.x;
    const int rb = blockIdx.y;
    const int z  = blockIdx.z;
    const int tid = threadIdx.x;
    const int row  = tid >> 1;
    const int colA = (tid & 1) * 16;
    const float* X = (z == 0) ? q : (z == 1) ? k : v;
    const float* p = X + (size_t)(rb * 128 + row) * EMB + c * 32 + colA;
    uint4* img = g_Ib + (size_t)((z * 16 + c) * 64 + rb) * 1024;
    const int u = colA >> 3;
    uint4 hi, lo;
    pack8(*(const float4*)p, *(const float4*)(p + 4), hi, lo);
    img[swz(row, u)]     = hi;
    img[swz(row, u + 4)] = lo;
    pack8(*(const float4*)(p + 8), *(const float4*)(p + 12), hi, lo);
    img[swz(row, u + 1)] = hi;
    img[swz(row, u + 5)] = lo;
}

// ---------------------------------------------------------------------------
// 3xFP16 GEMM. Block 128x64, BK=32, 256 thr (8 warps 4Mx2N), warptile 32x32.
// A and B both stream via cp.async from pre-split images (g_Ib/g_Ob, g_Wb).
// MODE 0 epilogue: Q (beta*log2e folded, hi only) / K,V (LayerNorm, hi+lo)
//                  -> split images.
// MODE 1 epilogue: fp32 + bias -> d_out.
// ---------------------------------------------------------------------------
template<int MODE>
__global__ __launch_bounds__(256)
void gemm_mma_kernel(const float* __restrict__ bfull, float* __restrict__ outp,
                     const float* __restrict__ pnw, const float* __restrict__ pnb,
                     const float* __restrict__ scaling)
{
    __shared__ uint4 ASm[2][1024];   // 32KB
    __shared__ uint4 BSm[2][512];    // 16KB

    const int tid    = threadIdx.x;
    const int warp   = tid >> 5;
    const int lane   = tid & 31;
    const int g      = lane >> 2;
    const int t      = lane & 3;
    const int warp_m = warp >> 1;
    const int warp_n = warp & 1;
    const int r0     = blockIdx.x * 128;
    const int f0     = blockIdx.y * 64;

    const int zW = (MODE == 0) ? blockIdx.z : 3;
    const uint4* Wt   = g_Wb + (size_t)(zW * 8 + blockIdx.y) * 16 * 512;
    const uint4* Aimg = (MODE == 0) ? (g_Ib + (size_t)blockIdx.z * 16 * 64 * 1024)
                                    : g_Ob;
    const float* bias = (MODE == 0) ? bfull + blockIdx.z * EMB : bfull;

    const unsigned aBase = smem_u32(ASm);
    const unsigned bBase = smem_u32(BSm);
    const int lm = lane >> 3;
    const int lr = lane & 7;

    float acc[2][4][4];
    #pragma unroll
    for (int mi = 0; mi < 2; mi++)
        #pragma unroll
        for (int ni = 0; ni < 4; ni++)
            #pragma unroll
            for (int j = 0; j < 4; j++) acc[mi][ni][j] = 0.f;

    // ---- prologue: chunk 0 ----
    {
        const uint4* Asrc = Aimg + (size_t)blockIdx.x * 1024;
        #pragma unroll
        for (int k = 0; k < 4; k++)
            cpa16(aBase + (tid + k * 256) * 16, Asrc + tid + k * 256);
        cpa16(bBase + tid * 16, Wt + tid);
        cpa16(bBase + (tid + 256) * 16, Wt + tid + 256);
        CPA_COMMIT();
    }

    for (int c = 0; c < 16; c++) {
        const int cur = c & 1, nxt = cur ^ 1;
        CPA_WAIT(0);
        __syncthreads();
        if (c + 1 < 16) {
            const uint4* Asrc = Aimg + (size_t)((c + 1) * 64 + blockIdx.x) * 1024;
            #pragma unroll
            for (int k = 0; k < 4; k++)
                cpa16(aBase + (nxt * 1024 + tid + k * 256) * 16, Asrc + tid + k * 256);
            const uint4* Bsrc = Wt + (size_t)(c + 1) * 512;
            cpa16(bBase + (nxt * 512 + tid) * 16, Bsrc + tid);
            cpa16(bBase + (nxt * 512 + tid + 256) * 16, Bsrc + tid + 256);
            CPA_COMMIT();
        }

        const unsigned aOff = aBase + cur * (1024 * 16);
        const unsigned bOff = bBase + cur * (512 * 16);
        #pragma unroll
        for (int ks = 0; ks < 2; ks++) {
            uint4 ah[2], al[2], bh[2], bl[2];
            #pragma unroll
            for (int mi = 0; mi < 2; mi++) {
                const int row = warp_m * 32 + mi * 16 + ((lm & 1) << 3) + lr;
                const int u   = ks * 2 + (lm >> 1);
                ldsm4(ah[mi], aOff + swz(row, u) * 16);
                ldsm4(al[mi], aOff + swz(row, u + 4) * 16);
            }
            #pragma unroll
            for (int bi = 0; bi < 2; bi++) {
                const int row = warp_n * 32 + bi * 16 + ((lm >> 1) << 3) + lr;
                const int u   = ks * 2 + (lm & 1);
                ldsm4(bh[bi], bOff + swz(row, u) * 16);
                ldsm4(bl[bi], bOff + swz(row, u + 4) * 16);
            }
            #pragma unroll
            for (int ni = 0; ni < 4; ni++) {
                const int bi = ni >> 1;
                const unsigned h0 = (ni & 1) ? bh[bi].z : bh[bi].x;
                const unsigned h1 = (ni & 1) ? bh[bi].w : bh[bi].y;
                const unsigned l0 = (ni & 1) ? bl[bi].z : bl[bi].x;
                const unsigned l1 = (ni & 1) ? bl[bi].w : bl[bi].y;
                #pragma unroll
                for (int mi = 0; mi < 2; mi++) {
                    mma_f16(acc[mi][ni], &ah[mi].x, h0, h1);
                    mma_f16(acc[mi][ni], &ah[mi].x, l0, l1);
                    mma_f16(acc[mi][ni], &al[mi].x, h0, h1);
                }
            }
        }
    }

    // ---- epilogue ----
    if (MODE == 0) {
        const int z = blockIdx.z;
        const int h = (f0 + warp_n * 32) >> 5;
        unsigned* dw = (unsigned*)((z == 0) ? g_Qb : (z == 1) ? g_Kb : g_Vb);
        const bool doLN = (z != 0);
        const float qscale = doLN ? 1.0f : scaling[h] * 1.4426950408889634f;
        float pwv[8], pbv[8];
        if (doLN) {
            #pragma unroll
            for (int ni = 0; ni < 4; ni++) {
                const int d = ni * 8 + 2 * t;
                pwv[ni * 2]     = pnw[d];
                pwv[ni * 2 + 1] = pnw[d + 1];
                pbv[ni * 2]     = pnb[d];
                pbv[ni * 2 + 1] = pnb[d + 1];
            }
        }
        #pragma unroll
        for (int mi = 0; mi < 2; mi++) {
            float vals[2][8];
            #pragma unroll
            for (int ni = 0; ni < 4; ni++) {
                const int f = f0 + warp_n * 32 + ni * 8 + 2 * t;
                const float b0 = bias[f];
                const float b1 = bias[f + 1];
                vals[0][ni * 2]     = acc[mi][ni][0] + b0;
                vals[0][ni * 2 + 1] = acc[mi][ni][1] + b1;
                vals[1][ni * 2]     = acc[mi][ni][2] + b0;
                vals[1][ni * 2 + 1] = acc[mi][ni][3] + b1;
            }
            #pragma unroll
            for (int rh = 0; rh < 2; rh++) {
                if (doLN) {
                    float s = 0.f, s2 = 0.f;
                    #pragma unroll
                    for (int j = 0; j < 8; j++) {
                        s  += vals[rh][j];
                        s2 += vals[rh][j] * vals[rh][j];
                    }
                    s  += __shfl_xor_sync(0xffffffffu, s, 1);
                    s  += __shfl_xor_sync(0xffffffffu, s, 2);
                    s2 += __shfl_xor_sync(0xffffffffu, s2, 1);
                    s2 += __shfl_xor_sync(0xffffffffu, s2, 2);
                    const float mu  = s * (1.0f / HD);
                    const float var = s2 * (1.0f / HD) - mu * mu;
                    const float inv = rsqrtf(var + 1e-5f);
                    #pragma unroll
                    for (int j = 0; j < 8; j++)
                        vals[rh][j] = (vals[rh][j] - mu) * inv * pwv[j] + pbv[j];
                } else {
                    #pragma unroll
                    for (int j = 0; j < 8; j++) vals[rh][j] *= qscale;
                }
                const int r = r0 + warp_m * 32 + mi * 16 + g + rh * 8;
                const int l = r >> 2, n = r & 3;
                const unsigned base = ((unsigned)(n * NH + h) * 32 + (l >> 6)) * 512;
                const int rowc = l & 63;
                if (doLN) {
                    #pragma unroll
                    for (int ni = 0; ni < 4; ni++) {
                        unsigned hi, lo;
                        hsplit2(vals[rh][ni * 2], vals[rh][ni * 2 + 1], hi, lo);
                        dw[(base + swz(rowc, ni)) * 4 + t]     = hi;
                        dw[(base + swz(rowc, ni + 4)) * 4 + t] = lo;
                    }
                } else {
                    // Q: attention reads only the hi image (2-MMA QK)
                    #pragma unroll
                    for (int ni = 0; ni < 4; ni++)
                        dw[(base + swz(rowc, ni)) * 4 + t] =
                            hpack2(vals[rh][ni * 2], vals[rh][ni * 2 + 1]);
                }
            }
        }
    } else {
        #pragma unroll
        for (int mi = 0; mi < 2; mi++) {
            const int rA = r0 + warp_m * 32 + mi * 16 + g;
            const int rB = rA + 8;
            #pragma unroll
            for (int ni = 0; ni < 4; ni++) {
                const float* c = acc[mi][ni];
                const int f  = f0 + warp_n * 32 + ni * 8 + 2 * t;
                const float b0 = bias[f];
                const float b1 = bias[f + 1];
                *(float2*)(outp + (size_t)rA * EMB + f) = make_float2(c[0] + b0, c[1] + b1);
                *(float2*)(outp + (size_t)rB * EMB + f) = make_float2(c[2] + b0, c[3] + b1);
            }
        }
    }
}

// ---------------------------------------------------------------------------
// Flash attention: pre-split fp16 hi/lo K/V, fp16 Q (hi only), ring-3 cp.async.
// QK = Qh*Kh + Qh*Kl   (K exact; Q rounded once at 2^-11)
// PV = Ph*Vh + Ph*Vl   (V exact; P rounded once at 2^-11)
// Softmax via ex2.approx. Block 256 thr (8 warps), 16 q rows/warp,
// S-chunks of 64, grid (16, 64).
// ---------------------------------------------------------------------------
__global__ __launch_bounds__(256)
void attn_mma_kernel()
{
    __shared__ uint4 KV[3][1024];   // [stage][K 0..511 | V 512..1023], 48KB

    const int tid  = threadIdx.x;
    const int warp = tid >> 5;
    const int lane = tid & 31;
    const int g    = lane >> 2;
    const int t    = lane & 3;
    const int nh   = blockIdx.y;
    const int q0   = blockIdx.x * 128 + warp * 16;

    const unsigned kvB = smem_u32(KV);
    const int lm = lane >> 3;
    const int lr = lane & 7;

    // Q hi-fragments from the split image
    const unsigned* Qw = (const unsigned*)g_Qb;
    const unsigned qbase = ((unsigned)nh * 32 + (q0 >> 6)) * 512;
    const int rc = q0 & 63;
    unsigned aqh[2][4];
    #pragma unroll
    for (int ks = 0; ks < 2; ks++) {
        aqh[ks][0] = Qw[(qbase + swz(rc + g,     2 * ks)) * 4 + t];
        aqh[ks][1] = Qw[(qbase + swz(rc + g + 8, 2 * ks)) * 4 + t];
        aqh[ks][2] = Qw[(qbase + swz(rc + g,     2 * ks + 1)) * 4 + t];
        aqh[ks][3] = Qw[(qbase + swz(rc + g + 8, 2 * ks + 1)) * 4 + t];
    }

    float m0 = -1e30f, m1 = -1e30f, l0 = 0.f, l1 = 0.f;
    float o[4][4];
    #pragma unroll
    for (int nd = 0; nd < 4; nd++)
        #pragma unroll
        for (int j = 0; j < 4; j++) o[nd][j] = 0.f;

    const uint4* Ksrc = g_Kb + (size_t)nh * 32 * 512;
    const uint4* Vsrc = g_Vb + (size_t)nh * 32 * 512;

    cpa16(kvB + tid * 16,               Ksrc + tid);
    cpa16(kvB + (tid + 256) * 16,       Ksrc + tid + 256);
    cpa16(kvB + (512 + tid) * 16,       Vsrc + tid);
    cpa16(kvB + (512 + tid + 256) * 16, Vsrc + tid + 256);
    CPA_COMMIT();

    int st = 0;
    for (int c = 0; c < 32; c++) {
        if (c + 1 < 32) {
            const int ns = (st + 1 == 3) ? 0 : st + 1;
            const unsigned dB = kvB + ns * 16384;
            const uint4* Kc = Ksrc + (size_t)(c + 1) * 512;
            const uint4* Vc = Vsrc + (size_t)(c + 1) * 512;
            cpa16(dB + tid * 16,               Kc + tid);
            cpa16(dB + (tid + 256) * 16,       Kc + tid + 256);
            cpa16(dB + (512 + tid) * 16,       Vc + tid);
            cpa16(dB + (512 + tid + 256) * 16, Vc + tid + 256);
            CPA_COMMIT();
            CPA_WAIT(1);
        } else {
            CPA_WAIT(0);
        }
        __syncthreads();

        const unsigned ksb = kvB + st * 16384;
        const unsigned vsb = ksb + 8192;

        // ---- QK scores (2xFP16): 8 s-tiles of 16x8 ----
        float sc[8][4];
        #pragma unroll
        for (int nd = 0; nd < 8; nd++) {
            sc[nd][0] = sc[nd][1] = sc[nd][2] = sc[nd][3] = 0.f;
            const int row = nd * 8 + lr;
            uint4 kh, kl;
            ldsm4(kh, ksb + swz(row, lm) * 16);
            ldsm4(kl, ksb + swz(row, lm + 4) * 16);
            mma_f16(sc[nd], aqh[0], kh.x, kh.y);
            mma_f16(sc[nd], aqh[1], kh.z, kh.w);
            mma_f16(sc[nd], aqh[0], kl.x, kl.y);
            mma_f16(sc[nd], aqh[1], kl.z, kl.w);
        }

        // ---- online softmax (exp2 domain) ----
        float t0 = -1e30f, t1 = -1e30f;
        #pragma unroll
        for (int nd = 0; nd < 8; nd++) {
            t0 = fmaxf(t0, fmaxf(sc[nd][0], sc[nd][1]));
            t1 = fmaxf(t1, fmaxf(sc[nd][2], sc[nd][3]));
        }
        t0 = fmaxf(t0, __shfl_xor_sync(0xffffffffu, t0, 1));
        t0 = fmaxf(t0, __shfl_xor_sync(0xffffffffu, t0, 2));
        t1 = fmaxf(t1, __shfl_xor_sync(0xffffffffu, t1, 1));
        t1 = fmaxf(t1, __shfl_xor_sync(0xffffffffu, t1, 2));

        const float nm0 = fmaxf(m0, t0);
        const float nm1 = fmaxf(m1, t1);
        const float c0  = ex2f(m0 - nm0);
        const float c1  = ex2f(m1 - nm1);

        float rs0 = 0.f, rs1 = 0.f;
        #pragma unroll
        for (int nd = 0; nd < 8; nd++) {
            sc[nd][0] = ex2f(sc[nd][0] - nm0);
            sc[nd][1] = ex2f(sc[nd][1] - nm0);
            sc[nd][2] = ex2f(sc[nd][2] - nm1);
            sc[nd][3] = ex2f(sc[nd][3] - nm1);
            rs0 += sc[nd][0] + sc[nd][1];
            rs1 += sc[nd][2] + sc[nd][3];
        }
        rs0 += __shfl_xor_sync(0xffffffffu, rs0, 1);
        rs0 += __shfl_xor_sync(0xffffffffu, rs0, 2);
        rs1 += __shfl_xor_sync(0xffffffffu, rs1, 1);
        rs1 += __shfl_xor_sync(0xffffffffu, rs1, 2);

        l0 = l0 * c0 + rs0;
        l1 = l1 * c1 + rs1;
        #pragma unroll
        for (int nd = 0; nd < 4; nd++) {
            o[nd][0] *= c0; o[nd][1] *= c0;
            o[nd][2] *= c1; o[nd][3] *= c1;
        }
        m0 = nm0; m1 = nm1;

        // ---- PV (2xFP16): P packed once, V hi+lo ----
        #pragma unroll
        for (int kb = 0; kb < 4; kb++) {
            unsigned ph[4];
            ph[0] = hpack2(sc[2 * kb][0],     sc[2 * kb][1]);
            ph[1] = hpack2(sc[2 * kb][2],     sc[2 * kb][3]);
            ph[2] = hpack2(sc[2 * kb + 1][0], sc[2 * kb + 1][1]);
            ph[3] = hpack2(sc[2 * kb + 1][2], sc[2 * kb + 1][3]);
            #pragma unroll
            for (int dp = 0; dp < 2; dp++) {
                const int row = kb * 16 + ((lm & 1) << 3) + lr;
                const int u   = dp * 2 + (lm >> 1);
                uint4 vh, vl;
                ldsm4t(vh, vsb + swz(row, u) * 16);
                ldsm4t(vl, vsb + swz(row, u + 4) * 16);
                mma_f16(o[2 * dp],     ph, vh.x, vh.y);
                mma_f16(o[2 * dp],     ph, vl.x, vl.y);
                mma_f16(o[2 * dp + 1], ph, vh.z, vh.w);
                mma_f16(o[2 * dp + 1], ph, vl.z, vl.w);
            }
        }

        st = (st + 1 == 3) ? 0 : st + 1;
    }

    // ---- epilogue: write O in gemm<1>'s A-tile image (fp16 hi/lo) ----
    const float i0 = 1.0f / l0;
    const float i1 = 1.0f / l1;
    const int n = nh >> 4;
    const int h = nh & (NH - 1);
    unsigned* Ow = (unsigned*)g_Ob;
    #pragma unroll
    for (int rh = 0; rh < 2; rh++) {
        const int r = (q0 + g + rh * 8) * NB + n;
        const unsigned base = (unsigned)(h * 64 + (r >> 7)) * 1024;
        const int rowc = r & 127;
        const float inv = rh ? i1 : i0;
        #pragma unroll
        for (int nd = 0; nd < 4; nd++) {
            unsigned hi, lo;
            hsplit2(o[nd][rh * 2] * inv, o[nd][rh * 2 + 1] * inv, hi, lo);
            Ow[(base + swz(rowc, nd)) * 4 + t]     = hi;
            Ow[(base + swz(rowc, nd + 4)) * 4 + t] = lo;
        }
    }
}

// ---------------------------------------------------------------------------
extern "C" void kernel_launch(void* const* d_in, const int* in_sizes, int n_in,
                              void* d_out, int out_size)
{
    const float* query   = (const float*)d_in[0];
    const float* key_in  = (const float*)d_in[1];
    const float* value   = (const float*)d_in[2];
    const float* scaling = (const float*)d_in[3];
    const float* in_w    = (const float*)d_in[4];
    const float* in_b    = (const float*)d_in[5];
    const float* pn_w    = (const float*)d_in[6];
    const float* pn_b    = (const float*)d_in[7];
    const float* out_w   = (const float*)d_in[8];
    const float* out_b   = (const float*)d_in[9];
    float* out = (float*)d_out;

    // 0) weights + inputs -> fp16 hi/lo swizzled images
    prep_w_kernel<<<dim3(16, 8, 4), 256>>>(in_w, out_w);
    prep_x_kernel<<<dim3(16, 64, 3), 256>>>(query, key_in, value);

    // 1) QKV projections (+LN for K/V, +beta*log2e for Q) -> split images
    gemm_mma_kernel<0><<<dim3(ROWS / 128, EMB / 64, 3), 256>>>(
        in_b, nullptr, pn_w, pn_b, scaling);

    // 2) Flash attention -> O split image
    attn_mma_kernel<<<dim3(LQ / 128, NB * NH), 256>>>();

    // 3) Output projection -> d_out
    gemm_mma_kernel<1><<<dim3(ROWS / 128, EMB / 64, 1), 256>>>(
        out_b, out, nullptr, nullptr, nullptr);
}